// round 10
// baseline (speedup 1.0000x reference)
#include <cuda_runtime.h>
#include <cuda_bf16.h>
#include <cstdint>

#define NB 8
#define CC 256
#define NN 4096
#define DD 32
#define BQ 64
#define BK 64
#define NT (NN / BK)

// Pre-split bf16 operands (hi + lo; V hi-only: P*Vl term dropped, err ~5e-4)
__device__ __align__(128) __nv_bfloat16 g_qh[(size_t)NB * NN * DD];
__device__ __align__(128) __nv_bfloat16 g_ql[(size_t)NB * NN * DD];
__device__ __align__(128) __nv_bfloat16 g_kh[(size_t)NB * NN * DD];
__device__ __align__(128) __nv_bfloat16 g_kl[(size_t)NB * NN * DD];
__device__ __align__(128) __nv_bfloat16 g_vh[(size_t)NB * CC * NN];  // [b][c][n]

// ---- smem layout (dynamic, bytes) ----
#define QSTR 80                    // 32 bf16 + pad (20 words)
#define KSTR 80
#define PSTR 144                   // 64 bf16 + pad (36 words)
#define VSTR 144
#define OSTR 260                   // stage stride (floats)
#define QH_OFF 0
#define QL_OFF 5120
#define K_OFF(buf, mat) (10240 + (buf) * 10240 + (mat) * 5120)   // ends 30720
#define PH_OFF(buf) (30720 + (buf) * 18432)                      // 2 bufs, ends 67584
#define V_OFF(buf) (67584 + (buf) * 36864)                       // ends 141312
#define STAGE_OFF 67584            // reuses V region at epilogue (66560 <= 73728)
#define SMEM_BYTES 141312

// ---- helpers ----
__device__ __forceinline__ uint32_t smem_u32(const void* p) {
    uint32_t a;
    asm("{ .reg .u64 t; cvta.to.shared.u64 t, %1; cvt.u32.u64 %0, t; }" : "=r"(a) : "l"(p));
    return a;
}
__device__ __forceinline__ void cpa16(uint32_t dst, const void* src) {
    asm volatile("cp.async.cg.shared.global [%0], [%1], 16;" :: "r"(dst), "l"(src) : "memory");
}
__device__ __forceinline__ void cp_commit() { asm volatile("cp.async.commit_group;" ::: "memory"); }
template <int N> __device__ __forceinline__ void cp_wait() {
    asm volatile("cp.async.wait_group %0;" :: "n"(N) : "memory");
}
__device__ __forceinline__ void bar_pair(int id) {
    asm volatile("bar.sync %0, 64;" :: "r"(id) : "memory");
}
__device__ __forceinline__ void mma_bf16(float* d, const uint32_t* a, const uint32_t* b) {
    asm volatile(
        "mma.sync.aligned.m16n8k16.row.col.f32.bf16.bf16.f32 "
        "{%0,%1,%2,%3}, {%4,%5,%6,%7}, {%8,%9}, {%0,%1,%2,%3};"
        : "+f"(d[0]), "+f"(d[1]), "+f"(d[2]), "+f"(d[3])
        : "r"(a[0]), "r"(a[1]), "r"(a[2]), "r"(a[3]), "r"(b[0]), "r"(b[1]));
}
__device__ __forceinline__ uint32_t packbf(__nv_bfloat16 lo, __nv_bfloat16 hi) {
    __nv_bfloat162 t; t.x = lo; t.y = hi;
    return *(uint32_t*)&t;
}

// K tile load: 64 rows x 4 chunks x 2 mats = 512 chunks (2 per thread)
__device__ __forceinline__ void load_k(char* smp, int b, int m0, int buf, int tid) {
#pragma unroll
    for (int it = 0; it < 2; it++) {
        int idx = tid + it * 256;
        int mat = idx >> 8, r = (idx >> 2) & 63, j = idx & 3;
        const __nv_bfloat16* src = (mat ? g_kl : g_kh) +
            ((size_t)(b * NN + m0 + r)) * DD + j * 8;
        cpa16(smem_u32(smp + K_OFF(buf, mat) + r * KSTR + j * 16), src);
    }
}
// V tile load (hi only): 256 rows x 8 chunks = 2048 (8 per thread)
__device__ __forceinline__ void load_v(char* smp, int b, int m0, int buf, int tid) {
#pragma unroll
    for (int it = 0; it < 8; it++) {
        int idx = tid + it * 256;
        int r = idx >> 3, j = idx & 7;
        const __nv_bfloat16* src = g_vh + ((size_t)(b * CC + r)) * NN + m0 + j * 8;
        cpa16(smem_u32(smp + V_OFF(buf) + r * VSTR + j * 16), src);
    }
}

// One S micro-step (8 keys): 6 HMMA + exp + pack + P stores + own-frag keep
__device__ __forceinline__ void s_step(
    const char* smp_k_h, const char* smp_k_l, int krow, int tg,
    const uint32_t QhA[2][4], const uint32_t QlA[2][4],
    float& lsumA, float& lsumB,
    uint32_t* Ph_s, uint32_t* Pl_s,      // [2] own frags out
    char* ph_w, char* pl_w, int s)       // smem store bases (per-thread)
{
    uint32_t KhB[2][2], KlB[2][2];
#pragma unroll
    for (int kf = 0; kf < 2; kf++) {
        int w0 = (kf * 8 + tg) * 4;
        KhB[kf][0] = *(const uint32_t*)(smp_k_h + krow * KSTR + w0);
        KhB[kf][1] = *(const uint32_t*)(smp_k_h + krow * KSTR + w0 + 16);
        KlB[kf][0] = *(const uint32_t*)(smp_k_l + krow * KSTR + w0);
        KlB[kf][1] = *(const uint32_t*)(smp_k_l + krow * KSTR + w0 + 16);
    }
    float S[4] = {0.f, 0.f, 0.f, 0.f};
    mma_bf16(S, QhA[0], KhB[0]); mma_bf16(S, QhA[1], KhB[1]);
    mma_bf16(S, QlA[0], KhB[0]); mma_bf16(S, QlA[1], KhB[1]);
    mma_bf16(S, QhA[0], KlB[0]); mma_bf16(S, QhA[1], KlB[1]);

    float p0 = __expf(S[0]), p1 = __expf(S[1]);
    float p2 = __expf(S[2]), p3 = __expf(S[3]);
    lsumA += p0 + p1;
    lsumB += p2 + p3;
    __nv_bfloat16 h0 = __float2bfloat16(p0), h1 = __float2bfloat16(p1);
    __nv_bfloat16 h2 = __float2bfloat16(p2), h3 = __float2bfloat16(p3);
    uint32_t ph01 = packbf(h0, h1), ph23 = packbf(h2, h3);
    uint32_t pl01 = packbf(__float2bfloat16(p0 - __bfloat162float(h0)),
                           __float2bfloat16(p1 - __bfloat162float(h1)));
    uint32_t pl23 = packbf(__float2bfloat16(p2 - __bfloat162float(h2)),
                           __float2bfloat16(p3 - __bfloat162float(h3)));
    Ph_s[0] = ph01; Ph_s[1] = ph23;
    Pl_s[0] = pl01; Pl_s[1] = pl23;
    *(uint32_t*)(ph_w + s * 16)            = ph01;
    *(uint32_t*)(ph_w + 8 * PSTR + s * 16) = ph23;
    *(uint32_t*)(pl_w + s * 16)            = pl01;
    *(uint32_t*)(pl_w + 8 * PSTR + s * 16) = pl23;
}

// ---------------------------------------------------------------------------
// Projection: q/k -> [b][n][32] bf16 hi/lo
// ---------------------------------------------------------------------------
__global__ void __launch_bounds__(256) proj_qk(
    const float* __restrict__ W, const float* __restrict__ bias,
    const float* __restrict__ x,
    __nv_bfloat16* __restrict__ oh, __nv_bfloat16* __restrict__ ol)
{
    __shared__ float xs[32][128];
    __shared__ float ws[32][33];
    const int tid = threadIdx.x;
    const int b  = blockIdx.y;
    const int n0 = blockIdx.x * 128;
    const int tr = tid & 7, tn = tid >> 3;

    float acc[4][4];
#pragma unroll
    for (int i = 0; i < 4; i++) {
        float bb = bias[tr * 4 + i];
#pragma unroll
        for (int j = 0; j < 4; j++) acc[i][j] = bb;
    }
    for (int c0 = 0; c0 < CC; c0 += 32) {
#pragma unroll
        for (int k = 0; k < 16; k++) {
            int idx = tid + k * 256;
            int row = idx >> 7, col = idx & 127;
            xs[row][col] = x[((size_t)b * CC + (c0 + row)) * NN + n0 + col];
        }
#pragma unroll
        for (int k = 0; k < 4; k++) {
            int idx = tid + k * 256;
            int row = idx >> 5, col = idx & 31;
            ws[row][col] = W[(size_t)row * CC + c0 + col];
        }
        __syncthreads();
#pragma unroll 8
        for (int cc = 0; cc < 32; cc++) {
            float4 xv = *(const float4*)&xs[cc][tn * 4];
            float wr[4];
#pragma unroll
            for (int i = 0; i < 4; i++) wr[i] = ws[tr * 4 + i][cc];
#pragma unroll
            for (int i = 0; i < 4; i++) {
                acc[i][0] += wr[i] * xv.x; acc[i][1] += wr[i] * xv.y;
                acc[i][2] += wr[i] * xv.z; acc[i][3] += wr[i] * xv.w;
            }
        }
        __syncthreads();
    }
#pragma unroll
    for (int j = 0; j < 4; j++) {
        int n = n0 + tn * 4 + j;
#pragma unroll
        for (int i = 0; i < 4; i++) {
            int r = tr * 4 + i;
            float a = acc[i][j];
            __nv_bfloat16 h = __float2bfloat16(a);
            oh[((size_t)(b * NN + n)) * DD + r] = h;
            ol[((size_t)(b * NN + n)) * DD + r] = __float2bfloat16(a - __bfloat162float(h));
        }
    }
}

// ---------------------------------------------------------------------------
// Projection: v -> [b][c][n] bf16 (hi only)
// ---------------------------------------------------------------------------
__global__ void __launch_bounds__(256) proj_v(
    const float* __restrict__ W, const float* __restrict__ bias,
    const float* __restrict__ x,
    __nv_bfloat16* __restrict__ oh)
{
    __shared__ float xs[32][128];
    __shared__ float ws[32][33];
    const int tid = threadIdx.x;
    const int b  = blockIdx.y;
    const int n0 = blockIdx.x * 128;
    const int r0 = blockIdx.z * 32;
    const int tr = tid & 7, tn = tid >> 3;

    float acc[4][4];
#pragma unroll
    for (int i = 0; i < 4; i++) {
        float bb = bias[r0 + tr * 4 + i];
#pragma unroll
        for (int j = 0; j < 4; j++) acc[i][j] = bb;
    }
    for (int c0 = 0; c0 < CC; c0 += 32) {
#pragma unroll
        for (int k = 0; k < 16; k++) {
            int idx = tid + k * 256;
            int row = idx >> 7, col = idx & 127;
            xs[row][col] = x[((size_t)b * CC + (c0 + row)) * NN + n0 + col];
        }
#pragma unroll
        for (int k = 0; k < 4; k++) {
            int idx = tid + k * 256;
            int row = idx >> 5, col = idx & 31;
            ws[row][col] = W[(size_t)(r0 + row) * CC + c0 + col];
        }
        __syncthreads();
#pragma unroll 8
        for (int cc = 0; cc < 32; cc++) {
            float4 xv = *(const float4*)&xs[cc][tn * 4];
            float wr[4];
#pragma unroll
            for (int i = 0; i < 4; i++) wr[i] = ws[tr * 4 + i][cc];
#pragma unroll
            for (int i = 0; i < 4; i++) {
                acc[i][0] += wr[i] * xv.x; acc[i][1] += wr[i] * xv.y;
                acc[i][2] += wr[i] * xv.z; acc[i][3] += wr[i] * xv.w;
            }
        }
        __syncthreads();
    }
#pragma unroll
    for (int i = 0; i < 4; i++) {
        int r = r0 + tr * 4 + i;
#pragma unroll
        for (int j = 0; j < 4; j++) {
            int n = n0 + tn * 4 + j;
            oh[((size_t)(b * CC + r)) * NN + n] = __float2bfloat16(acc[i][j]);
        }
    }
}

// ---------------------------------------------------------------------------
// Flash attention: S(t+1) software-pipelined into PV(t) body (fills tensor-
// pipe bubbles). S de-duplicated across c-half warps; double-buffered P tile.
// Grid (NN/BQ, NB) = (64, 8); 256 threads = 8 warps (4 q-rows x 2 c-halves).
// ---------------------------------------------------------------------------
__global__ void __launch_bounds__(256, 1) flash_mma(
    const float* __restrict__ x, const float* __restrict__ gamma,
    float* __restrict__ out)
{
    extern __shared__ char smp[];
    const int tid  = threadIdx.x;
    const int lane = tid & 31;
    const int wid  = tid >> 5;
    const int wr   = wid >> 1;        // 0..3: q-rows  wr*16..+15
    const int wc   = wid & 1;         // 0..1: channel half AND key half for S
    const int g    = lane >> 2;
    const int tg   = lane & 3;
    const int b  = blockIdx.y;
    const int q0 = blockIdx.x * BQ;

    // ---- prologue group A: Q + K(0)->kbuf0 ----
#pragma unroll
    for (int it = 0; it < 2; it++) {
        int idx = tid + it * 256;
        int mat = idx >> 8, r = (idx >> 2) & 63, j = idx & 3;
        const __nv_bfloat16* src = (mat ? g_ql : g_qh) +
            ((size_t)(b * NN + q0 + r)) * DD + j * 8;
        cpa16(smem_u32(smp + (mat ? QL_OFF : QH_OFF) + r * QSTR + j * 16), src);
    }
    load_k(smp, b, 0, 0, tid);
    cp_commit();
    // ---- prologue group B: K(1)->kbuf1 + V(0)->vbuf0 ----
    load_k(smp, b, BK, 1, tid);
    load_v(smp, b, 0, 0, tid);
    cp_commit();

    cp_wait<1>();          // group A done (Q, K0)
    __syncthreads();

    // ---- Q fragments (constant across tiles) ----
    uint32_t QhA[2][4], QlA[2][4];
    {
        int rowA = wr * 16 + g, rowB = rowA + 8;
#pragma unroll
        for (int kf = 0; kf < 2; kf++) {
            int w0 = (kf * 8 + tg) * 4;
            QhA[kf][0] = *(const uint32_t*)(smp + QH_OFF + rowA * QSTR + w0);
            QhA[kf][1] = *(const uint32_t*)(smp + QH_OFF + rowB * QSTR + w0);
            QhA[kf][2] = *(const uint32_t*)(smp + QH_OFF + rowA * QSTR + w0 + 16);
            QhA[kf][3] = *(const uint32_t*)(smp + QH_OFF + rowB * QSTR + w0 + 16);
            QlA[kf][0] = *(const uint32_t*)(smp + QL_OFF + rowA * QSTR + w0);
            QlA[kf][1] = *(const uint32_t*)(smp + QL_OFF + rowB * QSTR + w0);
            QlA[kf][2] = *(const uint32_t*)(smp + QL_OFF + rowA * QSTR + w0 + 16);
            QlA[kf][3] = *(const uint32_t*)(smp + QL_OFF + rowB * QSTR + w0 + 16);
        }
    }

    float O[16][4];
#pragma unroll
    for (int i = 0; i < 16; i++)
#pragma unroll
        for (int j = 0; j < 4; j++) O[i][j] = 0.f;
    float lsumA = 0.f, lsumB = 0.f;
    uint32_t Ph[4][2], Pl[4][2];       // own P frags for current tile

    // loop-invariant per-thread P smem bases (buffer 0)
    const int rowA = wr * 16 + g;
    char* psh_w0 = smp + PH_OFF(0) + rowA * PSTR + (wc * 32 + 2 * tg) * 2;
    const char* psh_r0 = smp + PH_OFF(0) + rowA * PSTR + ((1 - wc) * 32 + 2 * tg) * 2;
    const int barid = 1 + wr;

    // ---- S(0) -> P buf0 ----
    {
        const char* kh = smp + K_OFF(0, 0);
        const char* kl = smp + K_OFF(0, 1);
#pragma unroll
        for (int s = 0; s < 4; s++)
            s_step(kh, kl, wc * 32 + s * 8 + g, tg, QhA, QlA,
                   lsumA, lsumB, Ph[s], Pl[s], psh_w0, psh_w0 + 9216, s);
    }
    bar_pair(barid);

    for (int t = 0; t < NT; t++) {
        __syncthreads();   // all warps done with prev-body smem reads
        if (t + 2 < NT) load_k(smp, b, (t + 2) * BK, t & 1, tid);
        if (t + 1 < NT) load_v(smp, b, (t + 1) * BK, (t + 1) & 1, tid);
        cp_commit();
        cp_wait<1>();      // G(t-1) done: K(t+1), V(t) resident
        __syncthreads();

        // ---- assemble full-width A-frags for tile t: own regs + partner smem ----
        const char* ph_r = psh_r0 + ((t & 1) ? 18432 : 0);
        const char* pl_r = ph_r + 9216;
        uint32_t APh[4][4], APl[4][4];
#pragma unroll
        for (int j = 0; j < 2; j++) {
            int kown = 2 * wc + j;
            APh[kown][0] = Ph[2*j][0];   APh[kown][1] = Ph[2*j][1];
            APh[kown][2] = Ph[2*j+1][0]; APh[kown][3] = Ph[2*j+1][1];
            APl[kown][0] = Pl[2*j][0];   APl[kown][1] = Pl[2*j][1];
            APl[kown][2] = Pl[2*j+1][0]; APl[kown][3] = Pl[2*j+1][1];
            int koth = 2 * (1 - wc) + j;
            APh[koth][0] = *(const uint32_t*)(ph_r + j * 32);
            APh[koth][1] = *(const uint32_t*)(ph_r + 8 * PSTR + j * 32);
            APh[koth][2] = *(const uint32_t*)(ph_r + j * 32 + 16);
            APh[koth][3] = *(const uint32_t*)(ph_r + 8 * PSTR + j * 32 + 16);
            APl[koth][0] = *(const uint32_t*)(pl_r + j * 32);
            APl[koth][1] = *(const uint32_t*)(pl_r + 8 * PSTR + j * 32);
            APl[koth][2] = *(const uint32_t*)(pl_r + j * 32 + 16);
            APl[koth][3] = *(const uint32_t*)(pl_r + 8 * PSTR + j * 32 + 16);
        }

        // ---- interleaved: PV(t) (16 steps) with S(t+1) (4 steps) ----
        const char* vh   = smp + V_OFF(t & 1);
        const char* kh_n = smp + K_OFF((t + 1) & 1, 0);
        const char* kl_n = smp + K_OFF((t + 1) & 1, 1);
        char* ph_w = psh_w0 + (((t + 1) & 1) ? 18432 : 0);
        char* pl_w = ph_w + 9216;
        const bool do_s = (t + 1 < NT);
#pragma unroll
        for (int nt = 0; nt < 16; nt++) {
            int crow = wc * 128 + nt * 8 + g;
            uint32_t VhB[4][2];
#pragma unroll
            for (int kf = 0; kf < 4; kf++) {
                int w0 = (kf * 8 + tg) * 4;
                VhB[kf][0] = *(const uint32_t*)(vh + crow * VSTR + w0);
                VhB[kf][1] = *(const uint32_t*)(vh + crow * VSTR + w0 + 16);
            }
#pragma unroll
            for (int kf = 0; kf < 4; kf++) {
                mma_bf16(O[nt], APh[kf], VhB[kf]);
                mma_bf16(O[nt], APl[kf], VhB[kf]);
            }
            if ((nt & 3) == 3 && do_s) {
                int s = nt >> 2;
                s_step(kh_n, kl_n, wc * 32 + s * 8 + g, tg, QhA, QlA,
                       lsumA, lsumB, Ph[s], Pl[s], ph_w, pl_w, s);
            }
        }
        if (do_s) bar_pair(barid);
    }

    // ---- combine lsum halves + epilogue ----
    lsumA += __shfl_xor_sync(0xffffffffu, lsumA, 1);
    lsumA += __shfl_xor_sync(0xffffffffu, lsumA, 2);
    lsumB += __shfl_xor_sync(0xffffffffu, lsumB, 1);
    lsumB += __shfl_xor_sync(0xffffffffu, lsumB, 2);

    __syncthreads();                          // all P/V reads done; reuse regions
    float* lsh = (float*)(smp + PH_OFF(0));   // 128 floats: [keyhalf][q]
    if (tg == 0) {
        lsh[wc * 64 + wr * 16 + g]     = lsumA;
        lsh[wc * 64 + wr * 16 + 8 + g] = lsumB;
    }
    float* stage = (float*)(smp + STAGE_OFF); // [q=64][c=256], stride OSTR
    {
        int q = wr * 16 + g;
#pragma unroll
        for (int nt = 0; nt < 16; nt++) {
            int c = wc * 128 + nt * 8 + tg * 2;
            stage[q * OSTR + c]           = O[nt][0];
            stage[q * OSTR + c + 1]       = O[nt][1];
            stage[(q + 8) * OSTR + c]     = O[nt][2];
            stage[(q + 8) * OSTR + c + 1] = O[nt][3];
        }
    }
    __syncthreads();
    const float gm = gamma[0];
    if (tid < 64) lsh[tid] = gm / (lsh[tid] + lsh[64 + tid]);   // per-q scale
    __syncthreads();

    {
        int c = tid;   // one channel row per thread
        const float* xr  = x   + ((size_t)(b * CC + c)) * NN + q0;
        float*       orw = out + ((size_t)(b * CC + c)) * NN + q0;
#pragma unroll 4
        for (int n4 = 0; n4 < 16; n4++) {
            float4 xv = *(const float4*)(xr + n4 * 4);
            float4 o;
            o.x = stage[(n4 * 4 + 0) * OSTR + c] * lsh[n4 * 4 + 0] + xv.x;
            o.y = stage[(n4 * 4 + 1) * OSTR + c] * lsh[n4 * 4 + 1] + xv.y;
            o.z = stage[(n4 * 4 + 2) * OSTR + c] * lsh[n4 * 4 + 2] + xv.z;
            o.w = stage[(n4 * 4 + 3) * OSTR + c] * lsh[n4 * 4 + 3] + xv.w;
            *(float4*)(orw + n4 * 4) = o;
        }
    }
}

// ---------------------------------------------------------------------------
extern "C" void kernel_launch(void* const* d_in, const int* in_sizes, int n_in,
                              void* d_out, int out_size)
{
    const float* x     = (const float*)d_in[0];
    const float* wq    = (const float*)d_in[1];
    const float* bq    = (const float*)d_in[2];
    const float* wk    = (const float*)d_in[3];
    const float* bk    = (const float*)d_in[4];
    const float* wv    = (const float*)d_in[5];
    const float* bv    = (const float*)d_in[6];
    const float* gamma = (const float*)d_in[7];
    float* out = (float*)d_out;

    __nv_bfloat16 *qh, *ql, *kh, *kl, *vh;
    cudaGetSymbolAddress((void**)&qh, g_qh);
    cudaGetSymbolAddress((void**)&ql, g_ql);
    cudaGetSymbolAddress((void**)&kh, g_kh);
    cudaGetSymbolAddress((void**)&kl, g_kl);
    cudaGetSymbolAddress((void**)&vh, g_vh);

    dim3 blk(256);
    proj_qk<<<dim3(NN / 128, NB), blk>>>(wq, bq, x, qh, ql);
    proj_qk<<<dim3(NN / 128, NB), blk>>>(wk, bk, x, kh, kl);
    proj_v <<<dim3(NN / 128, NB, CC / 32), blk>>>(wv, bv, x, vh);

    cudaFuncSetAttribute(flash_mma, cudaFuncAttributeMaxDynamicSharedMemorySize, SMEM_BYTES);
    flash_mma<<<dim3(NN / BQ, NB), blk, SMEM_BYTES>>>(x, gamma, out);
}

// round 11
// speedup vs baseline: 1.1953x; 1.1953x over previous
#include <cuda_runtime.h>
#include <cuda_bf16.h>
#include <cstdint>

#define NB 8
#define CC 256
#define NN 4096
#define DD 32
#define BQ 64
#define BK 64
#define NT (NN / BK)

// Pre-split bf16 operands (Q/K hi+lo, 3-term; V hi-only: P*Vl dropped, err ~5e-4)
__device__ __align__(128) __nv_bfloat16 g_qh[(size_t)NB * NN * DD];
__device__ __align__(128) __nv_bfloat16 g_ql[(size_t)NB * NN * DD];
__device__ __align__(128) __nv_bfloat16 g_kh[(size_t)NB * NN * DD];
__device__ __align__(128) __nv_bfloat16 g_kl[(size_t)NB * NN * DD];
__device__ __align__(128) __nv_bfloat16 g_vh[(size_t)NB * CC * NN];  // [b][c][n]

// ---- smem byte offsets (dynamic smem) ----
#define QSTR 80                    // 32 bf16 row + pad (20 words)
#define KSTR 80
#define VSTR 144                   // 64 bf16 row + pad (36 words)
#define OSTR 260                   // stage stride in floats
#define QH_OFF 0
#define QL_OFF 5120
#define K_OFF(buf, mat) (10240 + (buf) * 10240 + (mat) * 5120)   // ends 30720
#define V_OFF(buf) (30720 + (buf) * 36864)                       // ends 104448
#define STAGE_OFF 30720            // reuses V region at epilogue (66560 <= 73728)
#define SMEM_BYTES 104448

// ---- helpers ----
__device__ __forceinline__ uint32_t smem_u32(const void* p) {
    uint32_t a;
    asm("{ .reg .u64 t; cvta.to.shared.u64 t, %1; cvt.u32.u64 %0, t; }" : "=r"(a) : "l"(p));
    return a;
}
__device__ __forceinline__ void cpa16(uint32_t dst, const void* src) {
    asm volatile("cp.async.cg.shared.global [%0], [%1], 16;" :: "r"(dst), "l"(src) : "memory");
}
__device__ __forceinline__ void cp_commit() { asm volatile("cp.async.commit_group;" ::: "memory"); }
template <int N> __device__ __forceinline__ void cp_wait() {
    asm volatile("cp.async.wait_group %0;" :: "n"(N) : "memory");
}
__device__ __forceinline__ void mma_bf16(float* d, const uint32_t* a, const uint32_t* b) {
    asm volatile(
        "mma.sync.aligned.m16n8k16.row.col.f32.bf16.bf16.f32 "
        "{%0,%1,%2,%3}, {%4,%5,%6,%7}, {%8,%9}, {%0,%1,%2,%3};"
        : "+f"(d[0]), "+f"(d[1]), "+f"(d[2]), "+f"(d[3])
        : "r"(a[0]), "r"(a[1]), "r"(a[2]), "r"(a[3]), "r"(b[0]), "r"(b[1]));
}
__device__ __forceinline__ uint32_t packbf(__nv_bfloat16 lo, __nv_bfloat16 hi) {
    __nv_bfloat162 t; t.x = lo; t.y = hi;
    return *(uint32_t*)&t;
}

// per-thread share of one K/V tile load (10 cp.async of 16B)
__device__ __forceinline__ void load_kv(char* smp, int b, int m0, int buf, int tid) {
#pragma unroll
    for (int it = 0; it < 2; it++) {            // K: 64 rows x 4 chunks x 2 mats
        int idx = tid + it * 256;
        int mat = idx >> 8, r = (idx >> 2) & 63, j = idx & 3;
        const __nv_bfloat16* src = (mat ? g_kl : g_kh) +
            ((size_t)(b * NN + m0 + r)) * DD + j * 8;
        cpa16(smem_u32(smp + K_OFF(buf, mat) + r * KSTR + j * 16), src);
    }
#pragma unroll
    for (int it = 0; it < 8; it++) {            // V hi only: 256 rows x 8 chunks
        int idx = tid + it * 256;
        int r = idx >> 3, j = idx & 7;
        const __nv_bfloat16* src = g_vh + ((size_t)(b * CC + r)) * NN + m0 + j * 8;
        cpa16(smem_u32(smp + V_OFF(buf) + r * VSTR + j * 16), src);
    }
}

// ---------------------------------------------------------------------------
// Projection: q/k -> [b][n][32] bf16 hi/lo
// ---------------------------------------------------------------------------
__global__ void __launch_bounds__(256) proj_qk(
    const float* __restrict__ W, const float* __restrict__ bias,
    const float* __restrict__ x,
    __nv_bfloat16* __restrict__ oh, __nv_bfloat16* __restrict__ ol)
{
    __shared__ float xs[32][128];
    __shared__ float ws[32][33];
    const int tid = threadIdx.x;
    const int b  = blockIdx.y;
    const int n0 = blockIdx.x * 128;
    const int tr = tid & 7, tn = tid >> 3;

    float acc[4][4];
#pragma unroll
    for (int i = 0; i < 4; i++) {
        float bb = bias[tr * 4 + i];
#pragma unroll
        for (int j = 0; j < 4; j++) acc[i][j] = bb;
    }
    for (int c0 = 0; c0 < CC; c0 += 32) {
#pragma unroll
        for (int k = 0; k < 16; k++) {
            int idx = tid + k * 256;
            int row = idx >> 7, col = idx & 127;
            xs[row][col] = x[((size_t)b * CC + (c0 + row)) * NN + n0 + col];
        }
#pragma unroll
        for (int k = 0; k < 4; k++) {
            int idx = tid + k * 256;
            int row = idx >> 5, col = idx & 31;
            ws[row][col] = W[(size_t)row * CC + c0 + col];
        }
        __syncthreads();
#pragma unroll 8
        for (int cc = 0; cc < 32; cc++) {
            float4 xv = *(const float4*)&xs[cc][tn * 4];
            float wr[4];
#pragma unroll
            for (int i = 0; i < 4; i++) wr[i] = ws[tr * 4 + i][cc];
#pragma unroll
            for (int i = 0; i < 4; i++) {
                acc[i][0] += wr[i] * xv.x; acc[i][1] += wr[i] * xv.y;
                acc[i][2] += wr[i] * xv.z; acc[i][3] += wr[i] * xv.w;
            }
        }
        __syncthreads();
    }
#pragma unroll
    for (int j = 0; j < 4; j++) {
        int n = n0 + tn * 4 + j;
#pragma unroll
        for (int i = 0; i < 4; i++) {
            int r = tr * 4 + i;
            float a = acc[i][j];
            __nv_bfloat16 h = __float2bfloat16(a);
            oh[((size_t)(b * NN + n)) * DD + r] = h;
            ol[((size_t)(b * NN + n)) * DD + r] = __float2bfloat16(a - __bfloat162float(h));
        }
    }
}

// ---------------------------------------------------------------------------
// Projection: v -> [b][c][n] bf16 (hi only)
// ---------------------------------------------------------------------------
__global__ void __launch_bounds__(256) proj_v(
    const float* __restrict__ W, const float* __restrict__ bias,
    const float* __restrict__ x,
    __nv_bfloat16* __restrict__ oh)
{
    __shared__ float xs[32][128];
    __shared__ float ws[32][33];
    const int tid = threadIdx.x;
    const int b  = blockIdx.y;
    const int n0 = blockIdx.x * 128;
    const int r0 = blockIdx.z * 32;
    const int tr = tid & 7, tn = tid >> 3;

    float acc[4][4];
#pragma unroll
    for (int i = 0; i < 4; i++) {
        float bb = bias[r0 + tr * 4 + i];
#pragma unroll
        for (int j = 0; j < 4; j++) acc[i][j] = bb;
    }
    for (int c0 = 0; c0 < CC; c0 += 32) {
#pragma unroll
        for (int k = 0; k < 16; k++) {
            int idx = tid + k * 256;
            int row = idx >> 7, col = idx & 127;
            xs[row][col] = x[((size_t)b * CC + (c0 + row)) * NN + n0 + col];
        }
#pragma unroll
        for (int k = 0; k < 4; k++) {
            int idx = tid + k * 256;
            int row = idx >> 5, col = idx & 31;
            ws[row][col] = W[(size_t)(r0 + row) * CC + c0 + col];
        }
        __syncthreads();
#pragma unroll 8
        for (int cc = 0; cc < 32; cc++) {
            float4 xv = *(const float4*)&xs[cc][tn * 4];
            float wr[4];
#pragma unroll
            for (int i = 0; i < 4; i++) wr[i] = ws[tr * 4 + i][cc];
#pragma unroll
            for (int i = 0; i < 4; i++) {
                acc[i][0] += wr[i] * xv.x; acc[i][1] += wr[i] * xv.y;
                acc[i][2] += wr[i] * xv.z; acc[i][3] += wr[i] * xv.w;
            }
        }
        __syncthreads();
    }
#pragma unroll
    for (int i = 0; i < 4; i++) {
        int r = r0 + tr * 4 + i;
#pragma unroll
        for (int j = 0; j < 4; j++) {
            int n = n0 + tn * 4 + j;
            oh[((size_t)(b * CC + r)) * NN + n] = __float2bfloat16(acc[i][j]);
        }
    }
}

// ---------------------------------------------------------------------------
// Flash attention via mma.sync — R4 barrier-free skeleton (duplicated S,
// register-resident P, no exchange) + V-hi-only PV (2 terms, 176 HMMA/tile).
// Grid (NN/BQ, NB) = (64, 8); 256 threads = 8 warps (4 q-rows x 2 c-halves).
// ---------------------------------------------------------------------------
__global__ void __launch_bounds__(256, 1) flash_mma(
    const float* __restrict__ x, const float* __restrict__ gamma,
    float* __restrict__ out)
{
    extern __shared__ char smp[];
    const int tid  = threadIdx.x;
    const int lane = tid & 31;
    const int wid  = tid >> 5;
    const int wr   = wid >> 1;        // 0..3: q-rows  wr*16..+15
    const int wc   = wid & 1;         // 0..1: channels wc*128..+127
    const int g    = lane >> 2;       // groupID
    const int tg   = lane & 3;        // threadID-in-group
    const int b  = blockIdx.y;
    const int q0 = blockIdx.x * BQ;

    // ---- prologue: Q + tile-0 K/V ----
#pragma unroll
    for (int it = 0; it < 2; it++) {       // Q: 64 rows x 4 chunks x 2 mats
        int idx = tid + it * 256;
        int mat = idx >> 8, r = (idx >> 2) & 63, j = idx & 3;
        const __nv_bfloat16* src = (mat ? g_ql : g_qh) +
            ((size_t)(b * NN + q0 + r)) * DD + j * 8;
        cpa16(smem_u32(smp + (mat ? QL_OFF : QH_OFF) + r * QSTR + j * 16), src);
    }
    load_kv(smp, b, 0, 0, tid);
    cp_commit();
    cp_wait<0>();
    __syncthreads();

    // ---- preload Q fragments (constant across tiles) ----
    uint32_t QhA[2][4], QlA[2][4];
    {
        int rowA = wr * 16 + g, rowB = rowA + 8;
#pragma unroll
        for (int kf = 0; kf < 2; kf++) {
            int w0 = (kf * 8 + tg) * 4;
            QhA[kf][0] = *(const uint32_t*)(smp + QH_OFF + rowA * QSTR + w0);
            QhA[kf][1] = *(const uint32_t*)(smp + QH_OFF + rowB * QSTR + w0);
            QhA[kf][2] = *(const uint32_t*)(smp + QH_OFF + rowA * QSTR + w0 + 16);
            QhA[kf][3] = *(const uint32_t*)(smp + QH_OFF + rowB * QSTR + w0 + 16);
            QlA[kf][0] = *(const uint32_t*)(smp + QL_OFF + rowA * QSTR + w0);
            QlA[kf][1] = *(const uint32_t*)(smp + QL_OFF + rowB * QSTR + w0);
            QlA[kf][2] = *(const uint32_t*)(smp + QL_OFF + rowA * QSTR + w0 + 16);
            QlA[kf][3] = *(const uint32_t*)(smp + QL_OFF + rowB * QSTR + w0 + 16);
        }
    }

    float O[16][4];
#pragma unroll
    for (int i = 0; i < 16; i++)
#pragma unroll
        for (int j = 0; j < 4; j++) O[i][j] = 0.f;
    float lsumA = 0.f, lsumB = 0.f;
    uint32_t Ph[8][2], Pl[8][2];

    for (int t = 0; t < NT; t++) {
        const int buf = t & 1;
        if (t) cp_wait<0>();
        __syncthreads();
        if (t + 1 < NT) { load_kv(smp, b, (t + 1) * BK, buf ^ 1, tid); cp_commit(); }

        // ---- S = Q K^T (both wc warps duplicate; barrier-free) + exp + pack ----
        const char* kh = smp + K_OFF(buf, 0);
        const char* kl = smp + K_OFF(buf, 1);
#pragma unroll
        for (int nt = 0; nt < 8; nt++) {
            int krow = nt * 8 + g;
            uint32_t KhB[2][2], KlB[2][2];
#pragma unroll
            for (int kf = 0; kf < 2; kf++) {
                int w0 = (kf * 8 + tg) * 4;
                KhB[kf][0] = *(const uint32_t*)(kh + krow * KSTR + w0);
                KhB[kf][1] = *(const uint32_t*)(kh + krow * KSTR + w0 + 16);
                KlB[kf][0] = *(const uint32_t*)(kl + krow * KSTR + w0);
                KlB[kf][1] = *(const uint32_t*)(kl + krow * KSTR + w0 + 16);
            }
            float S[4] = {0.f, 0.f, 0.f, 0.f};
            mma_bf16(S, QhA[0], KhB[0]); mma_bf16(S, QhA[1], KhB[1]);
            mma_bf16(S, QlA[0], KhB[0]); mma_bf16(S, QlA[1], KhB[1]);
            mma_bf16(S, QhA[0], KlB[0]); mma_bf16(S, QhA[1], KlB[1]);

            float p0 = __expf(S[0]), p1 = __expf(S[1]);
            float p2 = __expf(S[2]), p3 = __expf(S[3]);
            lsumA += p0 + p1;
            lsumB += p2 + p3;
            __nv_bfloat16 h0 = __float2bfloat16(p0), h1 = __float2bfloat16(p1);
            __nv_bfloat16 h2 = __float2bfloat16(p2), h3 = __float2bfloat16(p3);
            Ph[nt][0] = packbf(h0, h1);
            Ph[nt][1] = packbf(h2, h3);
            Pl[nt][0] = packbf(__float2bfloat16(p0 - __bfloat162float(h0)),
                               __float2bfloat16(p1 - __bfloat162float(h1)));
            Pl[nt][1] = packbf(__float2bfloat16(p2 - __bfloat162float(h2)),
                               __float2bfloat16(p3 - __bfloat162float(h3)));
        }

        // ---- O += P V^T (P in registers; Vh only, 2 terms) ----
        const char* vh = smp + V_OFF(buf);
#pragma unroll
        for (int nt = 0; nt < 16; nt++) {
            int crow = wc * 128 + nt * 8 + g;
            uint32_t VhB[4][2];
#pragma unroll
            for (int kf = 0; kf < 4; kf++) {
                int w0 = (kf * 8 + tg) * 4;
                VhB[kf][0] = *(const uint32_t*)(vh + crow * VSTR + w0);
                VhB[kf][1] = *(const uint32_t*)(vh + crow * VSTR + w0 + 16);
            }
#pragma unroll
            for (int kf = 0; kf < 4; kf++) {
                uint32_t Ah[4] = {Ph[2*kf][0], Ph[2*kf][1], Ph[2*kf+1][0], Ph[2*kf+1][1]};
                uint32_t Al[4] = {Pl[2*kf][0], Pl[2*kf][1], Pl[2*kf+1][0], Pl[2*kf+1][1]};
                mma_bf16(O[nt], Ah, VhB[kf]);
                mma_bf16(O[nt], Al, VhB[kf]);
            }
        }
    }

    // ---- normalize + epilogue ----
    lsumA += __shfl_xor_sync(0xffffffffu, lsumA, 1);
    lsumA += __shfl_xor_sync(0xffffffffu, lsumA, 2);
    lsumB += __shfl_xor_sync(0xffffffffu, lsumB, 1);
    lsumB += __shfl_xor_sync(0xffffffffu, lsumB, 2);
    const float gm = gamma[0];
    const float scA = gm / lsumA;
    const float scB = gm / lsumB;

    __syncthreads();                            // V reads done; reuse as stage
    float* stage = (float*)(smp + STAGE_OFF);   // [q=64][c=256], stride OSTR
    {
        int q = wr * 16 + g;
#pragma unroll
        for (int nt = 0; nt < 16; nt++) {
            int c = wc * 128 + nt * 8 + tg * 2;
            stage[q * OSTR + c]           = O[nt][0] * scA;
            stage[q * OSTR + c + 1]       = O[nt][1] * scA;
            stage[(q + 8) * OSTR + c]     = O[nt][2] * scB;
            stage[(q + 8) * OSTR + c + 1] = O[nt][3] * scB;
        }
    }
    __syncthreads();

    {
        int c = tid;   // one channel row per thread
        const float* xr  = x   + ((size_t)(b * CC + c)) * NN + q0;
        float*       orw = out + ((size_t)(b * CC + c)) * NN + q0;
#pragma unroll 4
        for (int n4 = 0; n4 < 16; n4++) {
            float4 xv = *(const float4*)(xr + n4 * 4);
            float4 o;
            o.x = stage[(n4 * 4 + 0) * OSTR + c] + xv.x;
            o.y = stage[(n4 * 4 + 1) * OSTR + c] + xv.y;
            o.z = stage[(n4 * 4 + 2) * OSTR + c] + xv.z;
            o.w = stage[(n4 * 4 + 3) * OSTR + c] + xv.w;
            *(float4*)(orw + n4 * 4) = o;
        }
    }
}

// ---------------------------------------------------------------------------
extern "C" void kernel_launch(void* const* d_in, const int* in_sizes, int n_in,
                              void* d_out, int out_size)
{
    const float* x     = (const float*)d_in[0];
    const float* wq    = (const float*)d_in[1];
    const float* bq    = (const float*)d_in[2];
    const float* wk    = (const float*)d_in[3];
    const float* bk    = (const float*)d_in[4];
    const float* wv    = (const float*)d_in[5];
    const float* bv    = (const float*)d_in[6];
    const float* gamma = (const float*)d_in[7];
    float* out = (float*)d_out;

    __nv_bfloat16 *qh, *ql, *kh, *kl, *vh;
    cudaGetSymbolAddress((void**)&qh, g_qh);
    cudaGetSymbolAddress((void**)&ql, g_ql);
    cudaGetSymbolAddress((void**)&kh, g_kh);
    cudaGetSymbolAddress((void**)&kl, g_kl);
    cudaGetSymbolAddress((void**)&vh, g_vh);

    dim3 blk(256);
    proj_qk<<<dim3(NN / 128, NB), blk>>>(wq, bq, x, qh, ql);
    proj_qk<<<dim3(NN / 128, NB), blk>>>(wk, bk, x, kh, kl);
    proj_v <<<dim3(NN / 128, NB, CC / 32), blk>>>(wv, bv, x, vh);

    cudaFuncSetAttribute(flash_mma, cudaFuncAttributeMaxDynamicSharedMemorySize, SMEM_BYTES);
    flash_mma<<<dim3(NN / BQ, NB), blk, SMEM_BYTES>>>(x, gamma, out);
}

// round 12
// speedup vs baseline: 1.3142x; 1.0995x over previous
#include <cuda_runtime.h>
#include <cuda_fp16.h>
#include <cstdint>

#define NB 8
#define CC 256
#define NN 4096
#define DD 32
#define BQ 64
#define BK 64
#define NT (NN / BK)

// fp16 operands: Q/K hi+lo (3-term S, ~exact); V single fp16 (err 4.9e-4);
// P single fp16 via online softmax (p in (0,1], fits fp16 exactly).
__device__ __align__(128) __half g_qh[(size_t)NB * NN * DD];
__device__ __align__(128) __half g_ql[(size_t)NB * NN * DD];
__device__ __align__(128) __half g_kh[(size_t)NB * NN * DD];
__device__ __align__(128) __half g_kl[(size_t)NB * NN * DD];
__device__ __align__(128) __half g_vh[(size_t)NB * CC * NN];  // [b][c][n]

// ---- smem byte offsets (dynamic smem) ----
#define QSTR 80                    // 32 fp16 row + pad (20 words)
#define KSTR 80
#define VSTR 144                   // 64 fp16 row + pad (36 words)
#define OSTR 260                   // stage stride in floats
#define QH_OFF 0
#define QL_OFF 5120
#define K_OFF(buf, mat) (10240 + (buf) * 10240 + (mat) * 5120)   // ends 30720
#define V_OFF(buf) (30720 + (buf) * 36864)                       // ends 104448
#define STAGE_OFF 30720            // reuses V region at epilogue
#define SMEM_BYTES 104448

// ---- helpers ----
__device__ __forceinline__ uint32_t smem_u32(const void* p) {
    uint32_t a;
    asm("{ .reg .u64 t; cvta.to.shared.u64 t, %1; cvt.u32.u64 %0, t; }" : "=r"(a) : "l"(p));
    return a;
}
__device__ __forceinline__ void cpa16(uint32_t dst, const void* src) {
    asm volatile("cp.async.cg.shared.global [%0], [%1], 16;" :: "r"(dst), "l"(src) : "memory");
}
__device__ __forceinline__ void cp_commit() { asm volatile("cp.async.commit_group;" ::: "memory"); }
template <int N> __device__ __forceinline__ void cp_wait() {
    asm volatile("cp.async.wait_group %0;" :: "n"(N) : "memory");
}
__device__ __forceinline__ void mma_f16(float* d, const uint32_t* a, const uint32_t* b) {
    asm volatile(
        "mma.sync.aligned.m16n8k16.row.col.f32.f16.f16.f32 "
        "{%0,%1,%2,%3}, {%4,%5,%6,%7}, {%8,%9}, {%0,%1,%2,%3};"
        : "+f"(d[0]), "+f"(d[1]), "+f"(d[2]), "+f"(d[3])
        : "r"(a[0]), "r"(a[1]), "r"(a[2]), "r"(a[3]), "r"(b[0]), "r"(b[1]));
}
__device__ __forceinline__ uint32_t packh(float a, float b) {
    __half2 t; t.x = __float2half_rn(a); t.y = __float2half_rn(b);
    return *(uint32_t*)&t;
}

// per-thread share of one K/V tile load (10 cp.async of 16B)
__device__ __forceinline__ void load_kv(char* smp, int b, int m0, int buf, int tid) {
#pragma unroll
    for (int it = 0; it < 2; it++) {            // K: 64 rows x 4 chunks x 2 mats
        int idx = tid + it * 256;
        int mat = idx >> 8, r = (idx >> 2) & 63, j = idx & 3;
        const __half* src = (mat ? g_kl : g_kh) +
            ((size_t)(b * NN + m0 + r)) * DD + j * 8;
        cpa16(smem_u32(smp + K_OFF(buf, mat) + r * KSTR + j * 16), src);
    }
#pragma unroll
    for (int it = 0; it < 8; it++) {            // V: 256 rows x 8 chunks
        int idx = tid + it * 256;
        int r = idx >> 3, j = idx & 7;
        const __half* src = g_vh + ((size_t)(b * CC + r)) * NN + m0 + j * 8;
        cpa16(smem_u32(smp + V_OFF(buf) + r * VSTR + j * 16), src);
    }
}

// ---------------------------------------------------------------------------
// Projection: q/k -> [b][n][32] fp16 hi/lo
// ---------------------------------------------------------------------------
__global__ void __launch_bounds__(256) proj_qk(
    const float* __restrict__ W, const float* __restrict__ bias,
    const float* __restrict__ x,
    __half* __restrict__ oh, __half* __restrict__ ol)
{
    __shared__ float xs[32][128];
    __shared__ float ws[32][33];
    const int tid = threadIdx.x;
    const int b  = blockIdx.y;
    const int n0 = blockIdx.x * 128;
    const int tr = tid & 7, tn = tid >> 3;

    float acc[4][4];
#pragma unroll
    for (int i = 0; i < 4; i++) {
        float bb = bias[tr * 4 + i];
#pragma unroll
        for (int j = 0; j < 4; j++) acc[i][j] = bb;
    }
    for (int c0 = 0; c0 < CC; c0 += 32) {
#pragma unroll
        for (int k = 0; k < 16; k++) {
            int idx = tid + k * 256;
            int row = idx >> 7, col = idx & 127;
            xs[row][col] = x[((size_t)b * CC + (c0 + row)) * NN + n0 + col];
        }
#pragma unroll
        for (int k = 0; k < 4; k++) {
            int idx = tid + k * 256;
            int row = idx >> 5, col = idx & 31;
            ws[row][col] = W[(size_t)row * CC + c0 + col];
        }
        __syncthreads();
#pragma unroll 8
        for (int cc = 0; cc < 32; cc++) {
            float4 xv = *(const float4*)&xs[cc][tn * 4];
            float wr[4];
#pragma unroll
            for (int i = 0; i < 4; i++) wr[i] = ws[tr * 4 + i][cc];
#pragma unroll
            for (int i = 0; i < 4; i++) {
                acc[i][0] += wr[i] * xv.x; acc[i][1] += wr[i] * xv.y;
                acc[i][2] += wr[i] * xv.z; acc[i][3] += wr[i] * xv.w;
            }
        }
        __syncthreads();
    }
#pragma unroll
    for (int j = 0; j < 4; j++) {
        int n = n0 + tn * 4 + j;
#pragma unroll
        for (int i = 0; i < 4; i++) {
            int r = tr * 4 + i;
            float a = acc[i][j];
            __half h = __float2half_rn(a);
            oh[((size_t)(b * NN + n)) * DD + r] = h;
            ol[((size_t)(b * NN + n)) * DD + r] = __float2half_rn(a - __half2float(h));
        }
    }
}

// ---------------------------------------------------------------------------
// Projection: v -> [b][c][n] fp16
// ---------------------------------------------------------------------------
__global__ void __launch_bounds__(256) proj_v(
    const float* __restrict__ W, const float* __restrict__ bias,
    const float* __restrict__ x,
    __half* __restrict__ oh)
{
    __shared__ float xs[32][128];
    __shared__ float ws[32][33];
    const int tid = threadIdx.x;
    const int b  = blockIdx.y;
    const int n0 = blockIdx.x * 128;
    const int r0 = blockIdx.z * 32;
    const int tr = tid & 7, tn = tid >> 3;

    float acc[4][4];
#pragma unroll
    for (int i = 0; i < 4; i++) {
        float bb = bias[r0 + tr * 4 + i];
#pragma unroll
        for (int j = 0; j < 4; j++) acc[i][j] = bb;
    }
    for (int c0 = 0; c0 < CC; c0 += 32) {
#pragma unroll
        for (int k = 0; k < 16; k++) {
            int idx = tid + k * 256;
            int row = idx >> 7, col = idx & 127;
            xs[row][col] = x[((size_t)b * CC + (c0 + row)) * NN + n0 + col];
        }
#pragma unroll
        for (int k = 0; k < 4; k++) {
            int idx = tid + k * 256;
            int row = idx >> 5, col = idx & 31;
            ws[row][col] = W[(size_t)(r0 + row) * CC + c0 + col];
        }
        __syncthreads();
#pragma unroll 8
        for (int cc = 0; cc < 32; cc++) {
            float4 xv = *(const float4*)&xs[cc][tn * 4];
            float wr[4];
#pragma unroll
            for (int i = 0; i < 4; i++) wr[i] = ws[tr * 4 + i][cc];
#pragma unroll
            for (int i = 0; i < 4; i++) {
                acc[i][0] += wr[i] * xv.x; acc[i][1] += wr[i] * xv.y;
                acc[i][2] += wr[i] * xv.z; acc[i][3] += wr[i] * xv.w;
            }
        }
        __syncthreads();
    }
#pragma unroll
    for (int i = 0; i < 4; i++) {
        int r = r0 + tr * 4 + i;
#pragma unroll
        for (int j = 0; j < 4; j++) {
            int n = n0 + tn * 4 + j;
            oh[((size_t)(b * CC + r)) * NN + n] = __float2half_rn(acc[i][j]);
        }
    }
}

// ---------------------------------------------------------------------------
// Flash attention: fp16 HMMA, online softmax (P,V single fp16, 112 HMMA/tile).
// Barrier-free skeleton (duplicated S, register P, no exchange).
// Grid (NN/BQ, NB) = (64, 8); 256 threads = 8 warps (4 q-rows x 2 c-halves).
// ---------------------------------------------------------------------------
__global__ void __launch_bounds__(256, 1) flash_mma(
    const float* __restrict__ x, const float* __restrict__ gamma,
    float* __restrict__ out)
{
    extern __shared__ char smp[];
    const int tid  = threadIdx.x;
    const int lane = tid & 31;
    const int wid  = tid >> 5;
    const int wr   = wid >> 1;        // 0..3: q-rows  wr*16..+15
    const int wc   = wid & 1;         // 0..1: channels wc*128..+127
    const int g    = lane >> 2;       // groupID
    const int tg   = lane & 3;        // threadID-in-group
    const int b  = blockIdx.y;
    const int q0 = blockIdx.x * BQ;

    // ---- prologue: Q + tile-0 K/V ----
#pragma unroll
    for (int it = 0; it < 2; it++) {       // Q: 64 rows x 4 chunks x 2 mats
        int idx = tid + it * 256;
        int mat = idx >> 8, r = (idx >> 2) & 63, j = idx & 3;
        const __half* src = (mat ? g_ql : g_qh) +
            ((size_t)(b * NN + q0 + r)) * DD + j * 8;
        cpa16(smem_u32(smp + (mat ? QL_OFF : QH_OFF) + r * QSTR + j * 16), src);
    }
    load_kv(smp, b, 0, 0, tid);
    cp_commit();
    cp_wait<0>();
    __syncthreads();

    // ---- preload Q fragments (constant across tiles) ----
    uint32_t QhA[2][4], QlA[2][4];
    {
        int rowA = wr * 16 + g, rowB = rowA + 8;
#pragma unroll
        for (int kf = 0; kf < 2; kf++) {
            int w0 = (kf * 8 + tg) * 4;
            QhA[kf][0] = *(const uint32_t*)(smp + QH_OFF + rowA * QSTR + w0);
            QhA[kf][1] = *(const uint32_t*)(smp + QH_OFF + rowB * QSTR + w0);
            QhA[kf][2] = *(const uint32_t*)(smp + QH_OFF + rowA * QSTR + w0 + 16);
            QhA[kf][3] = *(const uint32_t*)(smp + QH_OFF + rowB * QSTR + w0 + 16);
            QlA[kf][0] = *(const uint32_t*)(smp + QL_OFF + rowA * QSTR + w0);
            QlA[kf][1] = *(const uint32_t*)(smp + QL_OFF + rowB * QSTR + w0);
            QlA[kf][2] = *(const uint32_t*)(smp + QL_OFF + rowA * QSTR + w0 + 16);
            QlA[kf][3] = *(const uint32_t*)(smp + QL_OFF + rowB * QSTR + w0 + 16);
        }
    }

    float O[16][4];
#pragma unroll
    for (int i = 0; i < 16; i++)
#pragma unroll
        for (int j = 0; j < 4; j++) O[i][j] = 0.f;
    float lsumA = 0.f, lsumB = 0.f;
    float mA = -1e30f, mB = -1e30f;
    float Sst[8][4];
    uint32_t PA[8], PB[8];

    for (int t = 0; t < NT; t++) {
        const int buf = t & 1;
        if (t) cp_wait<0>();
        __syncthreads();
        if (t + 1 < NT) { load_kv(smp, b, (t + 1) * BK, buf ^ 1, tid); cp_commit(); }

        // ---- S = Q K^T (3 fp16 split terms), stage + track tile max ----
        const char* kh = smp + K_OFF(buf, 0);
        const char* kl = smp + K_OFF(buf, 1);
        float tmA = -1e30f, tmB = -1e30f;
#pragma unroll
        for (int nt = 0; nt < 8; nt++) {
            int krow = nt * 8 + g;
            uint32_t KhB[2][2], KlB[2][2];
#pragma unroll
            for (int kf = 0; kf < 2; kf++) {
                int w0 = (kf * 8 + tg) * 4;
                KhB[kf][0] = *(const uint32_t*)(kh + krow * KSTR + w0);
                KhB[kf][1] = *(const uint32_t*)(kh + krow * KSTR + w0 + 16);
                KlB[kf][0] = *(const uint32_t*)(kl + krow * KSTR + w0);
                KlB[kf][1] = *(const uint32_t*)(kl + krow * KSTR + w0 + 16);
            }
            float S[4] = {0.f, 0.f, 0.f, 0.f};
            mma_f16(S, QhA[0], KhB[0]); mma_f16(S, QhA[1], KhB[1]);
            mma_f16(S, QlA[0], KhB[0]); mma_f16(S, QlA[1], KhB[1]);
            mma_f16(S, QhA[0], KlB[0]); mma_f16(S, QhA[1], KlB[1]);
            Sst[nt][0] = S[0]; Sst[nt][1] = S[1];
            Sst[nt][2] = S[2]; Sst[nt][3] = S[3];
            tmA = fmaxf(tmA, fmaxf(S[0], S[1]));
            tmB = fmaxf(tmB, fmaxf(S[2], S[3]));
        }
        // quad max (tg 0..3 share the query row)
        tmA = fmaxf(tmA, __shfl_xor_sync(0xffffffffu, tmA, 1));
        tmA = fmaxf(tmA, __shfl_xor_sync(0xffffffffu, tmA, 2));
        tmB = fmaxf(tmB, __shfl_xor_sync(0xffffffffu, tmB, 1));
        tmB = fmaxf(tmB, __shfl_xor_sync(0xffffffffu, tmB, 2));
        float mAn = fmaxf(mA, tmA), mBn = fmaxf(mB, tmB);
        float cA = __expf(mA - mAn), cB = __expf(mB - mBn);
        mA = mAn; mB = mBn;
        lsumA *= cA; lsumB *= cB;
#pragma unroll
        for (int i = 0; i < 16; i++) {
            O[i][0] *= cA; O[i][1] *= cA;
            O[i][2] *= cB; O[i][3] *= cB;
        }
        // ---- exp + pack fp16 P ----
#pragma unroll
        for (int nt = 0; nt < 8; nt++) {
            float p0 = __expf(Sst[nt][0] - mA), p1 = __expf(Sst[nt][1] - mA);
            float p2 = __expf(Sst[nt][2] - mB), p3 = __expf(Sst[nt][3] - mB);
            lsumA += p0 + p1;
            lsumB += p2 + p3;
            PA[nt] = packh(p0, p1);
            PB[nt] = packh(p2, p3);
        }

        // ---- O += P V^T (single fp16 term) ----
        const char* vh = smp + V_OFF(buf);
#pragma unroll
        for (int nt = 0; nt < 16; nt++) {
            int crow = wc * 128 + nt * 8 + g;
            uint32_t VhB[4][2];
#pragma unroll
            for (int kf = 0; kf < 4; kf++) {
                int w0 = (kf * 8 + tg) * 4;
                VhB[kf][0] = *(const uint32_t*)(vh + crow * VSTR + w0);
                VhB[kf][1] = *(const uint32_t*)(vh + crow * VSTR + w0 + 16);
            }
#pragma unroll
            for (int kf = 0; kf < 4; kf++) {
                uint32_t Ah[4] = {PA[2*kf], PB[2*kf], PA[2*kf+1], PB[2*kf+1]};
                mma_f16(O[nt], Ah, VhB[kf]);
            }
        }
    }

    // ---- normalize + epilogue ----
    lsumA += __shfl_xor_sync(0xffffffffu, lsumA, 1);
    lsumA += __shfl_xor_sync(0xffffffffu, lsumA, 2);
    lsumB += __shfl_xor_sync(0xffffffffu, lsumB, 1);
    lsumB += __shfl_xor_sync(0xffffffffu, lsumB, 2);
    const float gm = gamma[0];
    const float scA = gm / lsumA;
    const float scB = gm / lsumB;

    __syncthreads();                            // V reads done; reuse as stage
    float* stage = (float*)(smp + STAGE_OFF);   // [q=64][c=256], stride OSTR
    {
        int q = wr * 16 + g;
#pragma unroll
        for (int nt = 0; nt < 16; nt++) {
            int c = wc * 128 + nt * 8 + tg * 2;
            stage[q * OSTR + c]           = O[nt][0] * scA;
            stage[q * OSTR + c + 1]       = O[nt][1] * scA;
            stage[(q + 8) * OSTR + c]     = O[nt][2] * scB;
            stage[(q + 8) * OSTR + c + 1] = O[nt][3] * scB;
        }
    }
    __syncthreads();

    {
        int c = tid;   // one channel row per thread
        const float* xr  = x   + ((size_t)(b * CC + c)) * NN + q0;
        float*       orw = out + ((size_t)(b * CC + c)) * NN + q0;
#pragma unroll 4
        for (int n4 = 0; n4 < 16; n4++) {
            float4 xv = *(const float4*)(xr + n4 * 4);
            float4 o;
            o.x = stage[(n4 * 4 + 0) * OSTR + c] + xv.x;
            o.y = stage[(n4 * 4 + 1) * OSTR + c] + xv.y;
            o.z = stage[(n4 * 4 + 2) * OSTR + c] + xv.z;
            o.w = stage[(n4 * 4 + 3) * OSTR + c] + xv.w;
            *(float4*)(orw + n4 * 4) = o;
        }
    }
}

// ---------------------------------------------------------------------------
extern "C" void kernel_launch(void* const* d_in, const int* in_sizes, int n_in,
                              void* d_out, int out_size)
{
    const float* x     = (const float*)d_in[0];
    const float* wq    = (const float*)d_in[1];
    const float* bq    = (const float*)d_in[2];
    const float* wk    = (const float*)d_in[3];
    const float* bk    = (const float*)d_in[4];
    const float* wv    = (const float*)d_in[5];
    const float* bv    = (const float*)d_in[6];
    const float* gamma = (const float*)d_in[7];
    float* out = (float*)d_out;

    __half *qh, *ql, *kh, *kl, *vh;
    cudaGetSymbolAddress((void**)&qh, g_qh);
    cudaGetSymbolAddress((void**)&ql, g_ql);
    cudaGetSymbolAddress((void**)&kh, g_kh);
    cudaGetSymbolAddress((void**)&kl, g_kl);
    cudaGetSymbolAddress((void**)&vh, g_vh);

    dim3 blk(256);
    proj_qk<<<dim3(NN / 128, NB), blk>>>(wq, bq, x, qh, ql);
    proj_qk<<<dim3(NN / 128, NB), blk>>>(wk, bk, x, kh, kl);
    proj_v <<<dim3(NN / 128, NB, CC / 32), blk>>>(wv, bv, x, vh);

    cudaFuncSetAttribute(flash_mma, cudaFuncAttributeMaxDynamicSharedMemorySize, SMEM_BYTES);
    flash_mma<<<dim3(NN / BQ, NB), blk, SMEM_BYTES>>>(x, gamma, out);
}

// round 13
// speedup vs baseline: 1.6518x; 1.2569x over previous
#include <cuda_runtime.h>
#include <cuda_fp16.h>
#include <cstdint>

#define NB 8
#define CC 256
#define NN 4096
#define DD 32
#define BQ 64
#define BK 64
#define NT (NN / BK)

// fp16 operands
__device__ __align__(128) __half g_xh[(size_t)NB * NN * CC];  // xT [b][n][c]
__device__ __align__(128) __half g_xl[(size_t)NB * NN * CC];
__device__ __align__(128) __half g_qh[(size_t)NB * NN * DD];
__device__ __align__(128) __half g_ql[(size_t)NB * NN * DD];
__device__ __align__(128) __half g_kh[(size_t)NB * NN * DD];
__device__ __align__(128) __half g_kl[(size_t)NB * NN * DD];
__device__ __align__(128) __half g_vh[(size_t)NB * CC * NN];  // [b][c][n]

// ---- flash smem ----
#define QSTR 80
#define KSTR 80
#define VSTR 144
#define OSTR 260
#define QH_OFF 0
#define QL_OFF 5120
#define K_OFF(buf, mat) (10240 + (buf) * 10240 + (mat) * 5120)
#define V_OFF(buf) (30720 + (buf) * 36864)
#define STAGE_OFF 30720
#define SMEM_BYTES 104448
// ---- proj_qk_mma smem ----
#define PQ_WH 0                      // [64][256] fp16, stride 528
#define PQ_WL 33792
#define PQ_XH 67584                  // [128][64] fp16, stride 144
#define PQ_XL 86016
#define PQ_SMEM 104448
// ---- proj_v_mma smem ----
#define PV_WH 0                      // [128][64] stride 144
#define PV_WL 18432
#define PV_XH 36864
#define PV_XL 55296
#define PV_SMEM 73728

// ---- helpers ----
__device__ __forceinline__ uint32_t smem_u32(const void* p) {
    uint32_t a;
    asm("{ .reg .u64 t; cvta.to.shared.u64 t, %1; cvt.u32.u64 %0, t; }" : "=r"(a) : "l"(p));
    return a;
}
__device__ __forceinline__ void cpa16(uint32_t dst, const void* src) {
    asm volatile("cp.async.cg.shared.global [%0], [%1], 16;" :: "r"(dst), "l"(src) : "memory");
}
__device__ __forceinline__ void cp_commit() { asm volatile("cp.async.commit_group;" ::: "memory"); }
template <int N> __device__ __forceinline__ void cp_wait() {
    asm volatile("cp.async.wait_group %0;" :: "n"(N) : "memory");
}
__device__ __forceinline__ void mma_f16(float* d, const uint32_t* a, const uint32_t* b) {
    asm volatile(
        "mma.sync.aligned.m16n8k16.row.col.f32.f16.f16.f32 "
        "{%0,%1,%2,%3}, {%4,%5,%6,%7}, {%8,%9}, {%0,%1,%2,%3};"
        : "+f"(d[0]), "+f"(d[1]), "+f"(d[2]), "+f"(d[3])
        : "r"(a[0]), "r"(a[1]), "r"(a[2]), "r"(a[3]), "r"(b[0]), "r"(b[1]));
}
__device__ __forceinline__ uint32_t packh(float a, float b) {
    __half2 t; t.x = __float2half_rn(a); t.y = __float2half_rn(b);
    return *(uint32_t*)&t;
}
__device__ __forceinline__ uint32_t packhh(__half a, __half b) {
    __half2 t; t.x = a; t.y = b;
    return *(uint32_t*)&t;
}

// ---------------------------------------------------------------------------
// split_x: x fp32 [b][c][n] -> xh/xl fp16 transposed [b][n][c]
// ---------------------------------------------------------------------------
__global__ void __launch_bounds__(256) split_x(
    const float* __restrict__ x, __half* __restrict__ xh, __half* __restrict__ xl)
{
    __shared__ float tile[64][65];
    const int tid = threadIdx.x;
    const int n0 = blockIdx.x * 64, c0 = blockIdx.y * 64, b = blockIdx.z;
#pragma unroll
    for (int it = 0; it < 16; it++) {
        int r = it * 4 + (tid >> 6);
        int col = tid & 63;
        tile[r][col] = x[((size_t)(b * CC + c0 + r)) * NN + n0 + col];
    }
    __syncthreads();
#pragma unroll
    for (int it = 0; it < 8; it++) {
        int idx = it * 256 + tid;
        int nrow = idx >> 5;
        int cp = idx & 31;
        float a0 = tile[cp * 2][nrow];
        float a1 = tile[cp * 2 + 1][nrow];
        __half h0 = __float2half_rn(a0), h1 = __float2half_rn(a1);
        size_t o = ((size_t)(b * NN + n0 + nrow)) * CC + c0 + cp * 2;
        *(uint32_t*)(xh + o) = packhh(h0, h1);
        *(uint32_t*)(xl + o) = packh(a0 - __half2float(h0), a1 - __half2float(h1));
    }
}

// ---------------------------------------------------------------------------
// proj_qk_mma: q/k = W x + b via fp16 HMMA (3-term exact).
// Grid (NN/128, NB), 256 thr. CTA: 128 n rows x 64 outs (32 q-d | 32 k-d).
// ---------------------------------------------------------------------------
__global__ void __launch_bounds__(256) proj_qk_mma(
    const float* __restrict__ wq, const float* __restrict__ bq,
    const float* __restrict__ wk, const float* __restrict__ bk,
    const __half* __restrict__ xh, const __half* __restrict__ xl,
    __half* __restrict__ qh, __half* __restrict__ ql,
    __half* __restrict__ kh, __half* __restrict__ kl)
{
    extern __shared__ char sm[];
    const int tid = threadIdx.x, lane = tid & 31, wid = tid >> 5;
    const int g = lane >> 2, tg = lane & 3;
    const int b = blockIdx.y, n0 = blockIdx.x * 128;

    // W (q rows 0..31, k rows 32..63) fp32 -> h/l fp16 smem [64][256] str 528
#pragma unroll
    for (int it = 0; it < 16; it++) {
        int idx4 = it * 256 + tid;
        int row = idx4 >> 6, col4 = idx4 & 63;
        const float* src = (row < 32) ? (wq + (size_t)row * CC + col4 * 4)
                                      : (wk + (size_t)(row - 32) * CC + col4 * 4);
        float4 v = *(const float4*)src;
        __half h0 = __float2half_rn(v.x), h1 = __float2half_rn(v.y);
        __half h2 = __float2half_rn(v.z), h3 = __float2half_rn(v.w);
        uint32_t base = row * 528 + col4 * 8;
        *(uint32_t*)(sm + PQ_WH + base)     = packhh(h0, h1);
        *(uint32_t*)(sm + PQ_WH + base + 4) = packhh(h2, h3);
        *(uint32_t*)(sm + PQ_WL + base)     = packh(v.x - __half2float(h0), v.y - __half2float(h1));
        *(uint32_t*)(sm + PQ_WL + base + 4) = packh(v.z - __half2float(h2), v.w - __half2float(h3));
    }

    float acc[8][4];
#pragma unroll
    for (int i = 0; i < 8; i++)
#pragma unroll
        for (int j = 0; j < 4; j++) acc[i][j] = 0.f;

    for (int kc = 0; kc < 4; kc++) {
        __syncthreads();
        // x chunk: rows n0..+127, cols kc*64..+63 -> [128][64] str 144
#pragma unroll
        for (int it = 0; it < 4; it++) {
            int idx = it * 256 + tid;
            int r = idx >> 3, j = idx & 7;
            size_t go = ((size_t)(b * NN + n0 + r)) * CC + kc * 64 + j * 8;
            cpa16(smem_u32(sm + PQ_XH + r * 144 + j * 16), xh + go);
            cpa16(smem_u32(sm + PQ_XL + r * 144 + j * 16), xl + go);
        }
        cp_commit();
        cp_wait<0>();
        __syncthreads();

        const int rowA = wid * 16 + g;
        uint32_t Ah[4][4], Al[4][4];
#pragma unroll
        for (int kf = 0; kf < 4; kf++) {
            int w0 = (kf * 8 + tg) * 4;
            const char* ph = sm + PQ_XH + rowA * 144 + w0;
            const char* pl = sm + PQ_XL + rowA * 144 + w0;
            Ah[kf][0] = *(const uint32_t*)ph;
            Ah[kf][1] = *(const uint32_t*)(ph + 8 * 144);
            Ah[kf][2] = *(const uint32_t*)(ph + 16);
            Ah[kf][3] = *(const uint32_t*)(ph + 8 * 144 + 16);
            Al[kf][0] = *(const uint32_t*)pl;
            Al[kf][1] = *(const uint32_t*)(pl + 8 * 144);
            Al[kf][2] = *(const uint32_t*)(pl + 16);
            Al[kf][3] = *(const uint32_t*)(pl + 8 * 144 + 16);
        }
#pragma unroll
        for (int nf = 0; nf < 8; nf++) {
#pragma unroll
            for (int kf = 0; kf < 4; kf++) {
                int w0 = kc * 128 + (kf * 8 + tg) * 4;
                const char* pb  = sm + PQ_WH + (nf * 8 + g) * 528 + w0;
                const char* pbl = sm + PQ_WL + (nf * 8 + g) * 528 + w0;
                uint32_t Bh[2] = {*(const uint32_t*)pb,  *(const uint32_t*)(pb + 16)};
                uint32_t Bl[2] = {*(const uint32_t*)pbl, *(const uint32_t*)(pbl + 16)};
                mma_f16(acc[nf], Ah[kf], Bh);
                mma_f16(acc[nf], Al[kf], Bh);
                mma_f16(acc[nf], Ah[kf], Bl);
            }
        }
    }

    // epilogue: + bias, split h/l, store [b][n][32]
    const int nA = n0 + wid * 16 + g;
#pragma unroll
    for (int nf = 0; nf < 8; nf++) {
        bool isq = nf < 4;
        int d = (isq ? nf : nf - 4) * 8 + tg * 2;
        const float* bias = isq ? bq : bk;
        __half* oh = isq ? qh : kh;
        __half* ol = isq ? ql : kl;
        float b0 = bias[d], b1 = bias[d + 1];
        float v0 = acc[nf][0] + b0, v1 = acc[nf][1] + b1;
        float v2 = acc[nf][2] + b0, v3 = acc[nf][3] + b1;
        __half h0 = __float2half_rn(v0), h1 = __float2half_rn(v1);
        __half h2 = __float2half_rn(v2), h3 = __float2half_rn(v3);
        size_t o0 = ((size_t)(b * NN + nA)) * DD + d;
        size_t o1 = ((size_t)(b * NN + nA + 8)) * DD + d;
        *(uint32_t*)(oh + o0) = packhh(h0, h1);
        *(uint32_t*)(ol + o0) = packh(v0 - __half2float(h0), v1 - __half2float(h1));
        *(uint32_t*)(oh + o1) = packhh(h2, h3);
        *(uint32_t*)(ol + o1) = packh(v2 - __half2float(h2), v3 - __half2float(h3));
    }
}

// ---------------------------------------------------------------------------
// proj_v_mma: v = W x + b via fp16 HMMA (3-term). Output fp16 [b][c][n].
// Grid (NN/128, CC/128, NB), 256 thr. CTA: 128 c x 128 n.
// ---------------------------------------------------------------------------
__global__ void __launch_bounds__(256) proj_v_mma(
    const float* __restrict__ wv, const float* __restrict__ bv,
    const __half* __restrict__ xh, const __half* __restrict__ xl,
    __half* __restrict__ vh)
{
    extern __shared__ char sm[];
    const int tid = threadIdx.x, lane = tid & 31, wid = tid >> 5;
    const int g = lane >> 2, tg = lane & 3;
    const int b = blockIdx.z, c0 = blockIdx.y * 128, n0 = blockIdx.x * 128;
    const int wm = wid >> 1, wn = wid & 1;

    float acc[2][8][4];
#pragma unroll
    for (int m = 0; m < 2; m++)
#pragma unroll
        for (int i = 0; i < 8; i++)
#pragma unroll
            for (int j = 0; j < 4; j++) acc[m][i][j] = 0.f;

    for (int kc = 0; kc < 4; kc++) {
        __syncthreads();
        // W chunk: rows c0..+127, cols kc*64..+63 fp32 -> h/l [128][64] str 144
#pragma unroll
        for (int it = 0; it < 8; it++) {
            int idx4 = it * 256 + tid;
            int row = idx4 >> 4, col4 = idx4 & 15;
            float4 v = *(const float4*)(wv + (size_t)(c0 + row) * CC + kc * 64 + col4 * 4);
            __half h0 = __float2half_rn(v.x), h1 = __float2half_rn(v.y);
            __half h2 = __float2half_rn(v.z), h3 = __float2half_rn(v.w);
            uint32_t base = row * 144 + col4 * 8;
            *(uint32_t*)(sm + PV_WH + base)     = packhh(h0, h1);
            *(uint32_t*)(sm + PV_WH + base + 4) = packhh(h2, h3);
            *(uint32_t*)(sm + PV_WL + base)     = packh(v.x - __half2float(h0), v.y - __half2float(h1));
            *(uint32_t*)(sm + PV_WL + base + 4) = packh(v.z - __half2float(h2), v.w - __half2float(h3));
        }
        // x chunk via cp.async
#pragma unroll
        for (int it = 0; it < 4; it++) {
            int idx = it * 256 + tid;
            int r = idx >> 3, j = idx & 7;
            size_t go = ((size_t)(b * NN + n0 + r)) * CC + kc * 64 + j * 8;
            cpa16(smem_u32(sm + PV_XH + r * 144 + j * 16), xh + go);
            cpa16(smem_u32(sm + PV_XL + r * 144 + j * 16), xl + go);
        }
        cp_commit();
        cp_wait<0>();
        __syncthreads();

#pragma unroll
        for (int kf = 0; kf < 4; kf++) {
            int w0 = (kf * 8 + tg) * 4;
            uint32_t Ah[2][4], Al[2][4];
#pragma unroll
            for (int mf = 0; mf < 2; mf++) {
                int rowA = wm * 32 + mf * 16 + g;
                const char* ph = sm + PV_WH + rowA * 144 + w0;
                const char* pl = sm + PV_WL + rowA * 144 + w0;
                Ah[mf][0] = *(const uint32_t*)ph;
                Ah[mf][1] = *(const uint32_t*)(ph + 8 * 144);
                Ah[mf][2] = *(const uint32_t*)(ph + 16);
                Ah[mf][3] = *(const uint32_t*)(ph + 8 * 144 + 16);
                Al[mf][0] = *(const uint32_t*)pl;
                Al[mf][1] = *(const uint32_t*)(pl + 8 * 144);
                Al[mf][2] = *(const uint32_t*)(pl + 16);
                Al[mf][3] = *(const uint32_t*)(pl + 8 * 144 + 16);
            }
#pragma unroll
            for (int nf = 0; nf < 8; nf++) {
                int rowB = wn * 64 + nf * 8 + g;
                const char* pb  = sm + PV_XH + rowB * 144 + w0;
                const char* pbl = sm + PV_XL + rowB * 144 + w0;
                uint32_t Bh[2] = {*(const uint32_t*)pb,  *(const uint32_t*)(pb + 16)};
                uint32_t Bl[2] = {*(const uint32_t*)pbl, *(const uint32_t*)(pbl + 16)};
#pragma unroll
                for (int mf = 0; mf < 2; mf++) {
                    mma_f16(acc[mf][nf], Ah[mf], Bh);
                    mma_f16(acc[mf][nf], Al[mf], Bh);
                    mma_f16(acc[mf][nf], Ah[mf], Bl);
                }
            }
        }
    }

    // epilogue: + bias, store fp16 [b][c][n]
#pragma unroll
    for (int mf = 0; mf < 2; mf++) {
        int c = c0 + wm * 32 + mf * 16 + g;
        float b0 = bv[c], b8 = bv[c + 8];
#pragma unroll
        for (int nf = 0; nf < 8; nf++) {
            int n = n0 + wn * 64 + nf * 8 + tg * 2;
            *(uint32_t*)(vh + ((size_t)(b * CC + c)) * NN + n) =
                packh(acc[mf][nf][0] + b0, acc[mf][nf][1] + b0);
            *(uint32_t*)(vh + ((size_t)(b * CC + c + 8)) * NN + n) =
                packh(acc[mf][nf][2] + b8, acc[mf][nf][3] + b8);
        }
    }
}

// per-thread share of one K/V tile load (10 cp.async of 16B)
__device__ __forceinline__ void load_kv(char* smp, int b, int m0, int buf, int tid) {
#pragma unroll
    for (int it = 0; it < 2; it++) {
        int idx = tid + it * 256;
        int mat = idx >> 8, r = (idx >> 2) & 63, j = idx & 3;
        const __half* src = (mat ? g_kl : g_kh) +
            ((size_t)(b * NN + m0 + r)) * DD + j * 8;
        cpa16(smem_u32(smp + K_OFF(buf, mat) + r * KSTR + j * 16), src);
    }
#pragma unroll
    for (int it = 0; it < 8; it++) {
        int idx = tid + it * 256;
        int r = idx >> 3, j = idx & 7;
        const __half* src = g_vh + ((size_t)(b * CC + r)) * NN + m0 + j * 8;
        cpa16(smem_u32(smp + V_OFF(buf) + r * VSTR + j * 16), src);
    }
}

// ---------------------------------------------------------------------------
// Flash attention: fp16 HMMA, online softmax with slack-2 lazy rescale.
// ---------------------------------------------------------------------------
__global__ void __launch_bounds__(256, 1) flash_mma(
    const float* __restrict__ x, const float* __restrict__ gamma,
    float* __restrict__ out)
{
    extern __shared__ char smp[];
    const int tid  = threadIdx.x;
    const int lane = tid & 31;
    const int wid  = tid >> 5;
    const int wr   = wid >> 1;
    const int wc   = wid & 1;
    const int g    = lane >> 2;
    const int tg   = lane & 3;
    const int b  = blockIdx.y;
    const int q0 = blockIdx.x * BQ;

#pragma unroll
    for (int it = 0; it < 2; it++) {
        int idx = tid + it * 256;
        int mat = idx >> 8, r = (idx >> 2) & 63, j = idx & 3;
        const __half* src = (mat ? g_ql : g_qh) +
            ((size_t)(b * NN + q0 + r)) * DD + j * 8;
        cpa16(smem_u32(smp + (mat ? QL_OFF : QH_OFF) + r * QSTR + j * 16), src);
    }
    load_kv(smp, b, 0, 0, tid);
    cp_commit();
    cp_wait<0>();
    __syncthreads();

    uint32_t QhA[2][4], QlA[2][4];
    {
        int rowA = wr * 16 + g, rowB = rowA + 8;
#pragma unroll
        for (int kf = 0; kf < 2; kf++) {
            int w0 = (kf * 8 + tg) * 4;
            QhA[kf][0] = *(const uint32_t*)(smp + QH_OFF + rowA * QSTR + w0);
            QhA[kf][1] = *(const uint32_t*)(smp + QH_OFF + rowB * QSTR + w0);
            QhA[kf][2] = *(const uint32_t*)(smp + QH_OFF + rowA * QSTR + w0 + 16);
            QhA[kf][3] = *(const uint32_t*)(smp + QH_OFF + rowB * QSTR + w0 + 16);
            QlA[kf][0] = *(const uint32_t*)(smp + QL_OFF + rowA * QSTR + w0);
            QlA[kf][1] = *(const uint32_t*)(smp + QL_OFF + rowB * QSTR + w0);
            QlA[kf][2] = *(const uint32_t*)(smp + QL_OFF + rowA * QSTR + w0 + 16);
            QlA[kf][3] = *(const uint32_t*)(smp + QL_OFF + rowB * QSTR + w0 + 16);
        }
    }

    float O[16][4];
#pragma unroll
    for (int i = 0; i < 16; i++)
#pragma unroll
        for (int j = 0; j < 4; j++) O[i][j] = 0.f;
    float lsumA = 0.f, lsumB = 0.f;
    float mA = -1e30f, mB = -1e30f;
    float Sst[8][4];
    uint32_t PA[8], PB[8];

    for (int t = 0; t < NT; t++) {
        const int buf = t & 1;
        if (t) cp_wait<0>();
        __syncthreads();
        if (t + 1 < NT) { load_kv(smp, b, (t + 1) * BK, buf ^ 1, tid); cp_commit(); }

        // ---- S (3 fp16 split terms) + tile max ----
        const char* kh = smp + K_OFF(buf, 0);
        const char* kl = smp + K_OFF(buf, 1);
        float tmA = -1e30f, tmB = -1e30f;
#pragma unroll
        for (int nt = 0; nt < 8; nt++) {
            int krow = nt * 8 + g;
            uint32_t KhB[2][2], KlB[2][2];
#pragma unroll
            for (int kf = 0; kf < 2; kf++) {
                int w0 = (kf * 8 + tg) * 4;
                KhB[kf][0] = *(const uint32_t*)(kh + krow * KSTR + w0);
                KhB[kf][1] = *(const uint32_t*)(kh + krow * KSTR + w0 + 16);
                KlB[kf][0] = *(const uint32_t*)(kl + krow * KSTR + w0);
                KlB[kf][1] = *(const uint32_t*)(kl + krow * KSTR + w0 + 16);
            }
            float S[4] = {0.f, 0.f, 0.f, 0.f};
            mma_f16(S, QhA[0], KhB[0]); mma_f16(S, QhA[1], KhB[1]);
            mma_f16(S, QlA[0], KhB[0]); mma_f16(S, QlA[1], KhB[1]);
            mma_f16(S, QhA[0], KlB[0]); mma_f16(S, QhA[1], KlB[1]);
            Sst[nt][0] = S[0]; Sst[nt][1] = S[1];
            Sst[nt][2] = S[2]; Sst[nt][3] = S[3];
            tmA = fmaxf(tmA, fmaxf(S[0], S[1]));
            tmB = fmaxf(tmB, fmaxf(S[2], S[3]));
        }
        tmA = fmaxf(tmA, __shfl_xor_sync(0xffffffffu, tmA, 1));
        tmA = fmaxf(tmA, __shfl_xor_sync(0xffffffffu, tmA, 2));
        tmB = fmaxf(tmB, __shfl_xor_sync(0xffffffffu, tmB, 1));
        tmB = fmaxf(tmB, __shfl_xor_sync(0xffffffffu, tmB, 2));

        // ---- lazy rescale: only when tile max exceeds slack ----
        bool upd = (tmA > mA + 2.0f) || (tmB > mB + 2.0f);
        if (__ballot_sync(0xffffffffu, upd)) {
            float mAn = fmaxf(mA, tmA), mBn = fmaxf(mB, tmB);
            float cA = __expf(mA - mAn), cB = __expf(mB - mBn);
            mA = mAn; mB = mBn;
            lsumA *= cA; lsumB *= cB;
#pragma unroll
            for (int i = 0; i < 16; i++) {
                O[i][0] *= cA; O[i][1] *= cA;
                O[i][2] *= cB; O[i][3] *= cB;
            }
        }
        // ---- exp + pack fp16 P (p <= e^2, fits fp16) ----
#pragma unroll
        for (int nt = 0; nt < 8; nt++) {
            float p0 = __expf(Sst[nt][0] - mA), p1 = __expf(Sst[nt][1] - mA);
            float p2 = __expf(Sst[nt][2] - mB), p3 = __expf(Sst[nt][3] - mB);
            lsumA += p0 + p1;
            lsumB += p2 + p3;
            PA[nt] = packh(p0, p1);
            PB[nt] = packh(p2, p3);
        }

        // ---- O += P V^T (single fp16 term) ----
        const char* vh = smp + V_OFF(buf);
#pragma unroll
        for (int nt = 0; nt < 16; nt++) {
            int crow = wc * 128 + nt * 8 + g;
            uint32_t VhB[4][2];
#pragma unroll
            for (int kf = 0; kf < 4; kf++) {
                int w0 = (kf * 8 + tg) * 4;
                VhB[kf][0] = *(const uint32_t*)(vh + crow * VSTR + w0);
                VhB[kf][1] = *(const uint32_t*)(vh + crow * VSTR + w0 + 16);
            }
#pragma unroll
            for (int kf = 0; kf < 4; kf++) {
                uint32_t Ah[4] = {PA[2*kf], PB[2*kf], PA[2*kf+1], PB[2*kf+1]};
                mma_f16(O[nt], Ah, VhB[kf]);
            }
        }
    }

    // ---- normalize + epilogue ----
    lsumA += __shfl_xor_sync(0xffffffffu, lsumA, 1);
    lsumA += __shfl_xor_sync(0xffffffffu, lsumA, 2);
    lsumB += __shfl_xor_sync(0xffffffffu, lsumB, 1);
    lsumB += __shfl_xor_sync(0xffffffffu, lsumB, 2);
    const float gm = gamma[0];
    const float scA = gm / lsumA;
    const float scB = gm / lsumB;

    __syncthreads();
    float* stage = (float*)(smp + STAGE_OFF);
    {
        int q = wr * 16 + g;
#pragma unroll
        for (int nt = 0; nt < 16; nt++) {
            int c = wc * 128 + nt * 8 + tg * 2;
            stage[q * OSTR + c]           = O[nt][0] * scA;
            stage[q * OSTR + c + 1]       = O[nt][1] * scA;
            stage[(q + 8) * OSTR + c]     = O[nt][2] * scB;
            stage[(q + 8) * OSTR + c + 1] = O[nt][3] * scB;
        }
    }
    __syncthreads();

    {
        int c = tid;
        const float* xr  = x   + ((size_t)(b * CC + c)) * NN + q0;
        float*       orw = out + ((size_t)(b * CC + c)) * NN + q0;
#pragma unroll 4
        for (int n4 = 0; n4 < 16; n4++) {
            float4 xv = *(const float4*)(xr + n4 * 4);
            float4 o;
            o.x = stage[(n4 * 4 + 0) * OSTR + c] + xv.x;
            o.y = stage[(n4 * 4 + 1) * OSTR + c] + xv.y;
            o.z = stage[(n4 * 4 + 2) * OSTR + c] + xv.z;
            o.w = stage[(n4 * 4 + 3) * OSTR + c] + xv.w;
            *(float4*)(orw + n4 * 4) = o;
        }
    }
}

// ---------------------------------------------------------------------------
extern "C" void kernel_launch(void* const* d_in, const int* in_sizes, int n_in,
                              void* d_out, int out_size)
{
    const float* x     = (const float*)d_in[0];
    const float* wq    = (const float*)d_in[1];
    const float* bq    = (const float*)d_in[2];
    const float* wk    = (const float*)d_in[3];
    const float* bk    = (const float*)d_in[4];
    const float* wv    = (const float*)d_in[5];
    const float* bv    = (const float*)d_in[6];
    const float* gamma = (const float*)d_in[7];
    float* out = (float*)d_out;

    __half *xhp, *xlp, *qh, *ql, *kh, *kl, *vh;
    cudaGetSymbolAddress((void**)&xhp, g_xh);
    cudaGetSymbolAddress((void**)&xlp, g_xl);
    cudaGetSymbolAddress((void**)&qh, g_qh);
    cudaGetSymbolAddress((void**)&ql, g_ql);
    cudaGetSymbolAddress((void**)&kh, g_kh);
    cudaGetSymbolAddress((void**)&kl, g_kl);
    cudaGetSymbolAddress((void**)&vh, g_vh);

    dim3 blk(256);
    split_x<<<dim3(NN / 64, CC / 64, NB), blk>>>(x, xhp, xlp);

    cudaFuncSetAttribute(proj_qk_mma, cudaFuncAttributeMaxDynamicSharedMemorySize, PQ_SMEM);
    proj_qk_mma<<<dim3(NN / 128, NB), blk, PQ_SMEM>>>(wq, bq, wk, bk, xhp, xlp, qh, ql, kh, kl);

    cudaFuncSetAttribute(proj_v_mma, cudaFuncAttributeMaxDynamicSharedMemorySize, PV_SMEM);
    proj_v_mma<<<dim3(NN / 128, CC / 128, NB), blk, PV_SMEM>>>(wv, bv, xhp, xlp, vh);

    cudaFuncSetAttribute(flash_mma, cudaFuncAttributeMaxDynamicSharedMemorySize, SMEM_BYTES);
    flash_mma<<<dim3(NN / BQ, NB), blk, SMEM_BYTES>>>(x, gamma, out);
}

// round 14
// speedup vs baseline: 1.7465x; 1.0573x over previous
#include <cuda_runtime.h>
#include <cuda_fp16.h>
#include <cstdint>

#define NB 8
#define CC 256
#define NN 4096
#define DD 32
#define BQ 64
#define BK 64
#define NT (NN / BK)

// fp16 operands (q pre-scaled by log2e so softmax uses exp2)
__device__ __align__(128) __half g_xh[(size_t)NB * NN * CC];  // xT [b][n][c]
__device__ __align__(128) __half g_xl[(size_t)NB * NN * CC];
__device__ __align__(128) __half g_qh[(size_t)NB * NN * DD];
__device__ __align__(128) __half g_ql[(size_t)NB * NN * DD];
__device__ __align__(128) __half g_kh[(size_t)NB * NN * DD];
__device__ __align__(128) __half g_kl[(size_t)NB * NN * DD];
__device__ __align__(128) __half g_vh[(size_t)NB * CC * NN];  // [b][c][n]

// ---- flash smem ----
#define QSTR 80
#define KSTR 80
#define VSTR 144
#define OSTR 260
#define QH_OFF 0
#define QL_OFF 5120
#define K_OFF(buf, mat) (10240 + (buf) * 10240 + (mat) * 5120)
#define V_OFF(buf) (30720 + (buf) * 36864)
#define STAGE_OFF 30720
#define SMEM_BYTES 104448
// ---- proj_qk_mma smem ----
#define PQ_WH 0
#define PQ_WL 33792
#define PQ_XH 67584
#define PQ_XL 86016
#define PQ_SMEM 104448
// ---- proj_v_mma smem ----
#define PV_WH 0
#define PV_WL 18432
#define PV_XH 36864
#define PV_XL 55296
#define PV_SMEM 73728

// ---- helpers ----
__device__ __forceinline__ uint32_t smem_u32(const void* p) {
    uint32_t a;
    asm("{ .reg .u64 t; cvta.to.shared.u64 t, %1; cvt.u32.u64 %0, t; }" : "=r"(a) : "l"(p));
    return a;
}
__device__ __forceinline__ void cpa16(uint32_t dst, const void* src) {
    asm volatile("cp.async.cg.shared.global [%0], [%1], 16;" :: "r"(dst), "l"(src) : "memory");
}
__device__ __forceinline__ void cp_commit() { asm volatile("cp.async.commit_group;" ::: "memory"); }
template <int N> __device__ __forceinline__ void cp_wait() {
    asm volatile("cp.async.wait_group %0;" :: "n"(N) : "memory");
}
__device__ __forceinline__ void mma_f16(float* d, const uint32_t* a, const uint32_t* b) {
    asm volatile(
        "mma.sync.aligned.m16n8k16.row.col.f32.f16.f16.f32 "
        "{%0,%1,%2,%3}, {%4,%5,%6,%7}, {%8,%9}, {%0,%1,%2,%3};"
        : "+f"(d[0]), "+f"(d[1]), "+f"(d[2]), "+f"(d[3])
        : "r"(a[0]), "r"(a[1]), "r"(a[2]), "r"(a[3]), "r"(b[0]), "r"(b[1]));
}
__device__ __forceinline__ uint32_t packh(float a, float b) {
    __half2 t; t.x = __float2half_rn(a); t.y = __float2half_rn(b);
    return *(uint32_t*)&t;
}
__device__ __forceinline__ uint32_t packhh(__half a, __half b) {
    __half2 t; t.x = a; t.y = b;
    return *(uint32_t*)&t;
}

// ---------------------------------------------------------------------------
// split_x: x fp32 [b][c][n] -> xh/xl fp16 transposed [b][n][c]
// ---------------------------------------------------------------------------
__global__ void __launch_bounds__(256) split_x(
    const float* __restrict__ x, __half* __restrict__ xh, __half* __restrict__ xl)
{
    __shared__ float tile[64][65];
    const int tid = threadIdx.x;
    const int n0 = blockIdx.x * 64, c0 = blockIdx.y * 64, b = blockIdx.z;
#pragma unroll
    for (int it = 0; it < 16; it++) {
        int r = it * 4 + (tid >> 6);
        int col = tid & 63;
        tile[r][col] = x[((size_t)(b * CC + c0 + r)) * NN + n0 + col];
    }
    __syncthreads();
#pragma unroll
    for (int it = 0; it < 8; it++) {
        int idx = it * 256 + tid;
        int nrow = idx >> 5;
        int cp = idx & 31;
        float a0 = tile[cp * 2][nrow];
        float a1 = tile[cp * 2 + 1][nrow];
        __half h0 = __float2half_rn(a0), h1 = __float2half_rn(a1);
        size_t o = ((size_t)(b * NN + n0 + nrow)) * CC + c0 + cp * 2;
        *(uint32_t*)(xh + o) = packhh(h0, h1);
        *(uint32_t*)(xl + o) = packh(a0 - __half2float(h0), a1 - __half2float(h1));
    }
}

// ---------------------------------------------------------------------------
// proj_qk_mma: q/k = W x + b via fp16 HMMA (3-term). q scaled by log2e.
// ---------------------------------------------------------------------------
__global__ void __launch_bounds__(256) proj_qk_mma(
    const float* __restrict__ wq, const float* __restrict__ bq,
    const float* __restrict__ wk, const float* __restrict__ bk,
    const __half* __restrict__ xh, const __half* __restrict__ xl,
    __half* __restrict__ qh, __half* __restrict__ ql,
    __half* __restrict__ kh, __half* __restrict__ kl)
{
    extern __shared__ char sm[];
    const int tid = threadIdx.x, lane = tid & 31, wid = tid >> 5;
    const int g = lane >> 2, tg = lane & 3;
    const int b = blockIdx.y, n0 = blockIdx.x * 128;

#pragma unroll
    for (int it = 0; it < 16; it++) {
        int idx4 = it * 256 + tid;
        int row = idx4 >> 6, col4 = idx4 & 63;
        const float* src = (row < 32) ? (wq + (size_t)row * CC + col4 * 4)
                                      : (wk + (size_t)(row - 32) * CC + col4 * 4);
        float4 v = *(const float4*)src;
        __half h0 = __float2half_rn(v.x), h1 = __float2half_rn(v.y);
        __half h2 = __float2half_rn(v.z), h3 = __float2half_rn(v.w);
        uint32_t base = row * 528 + col4 * 8;
        *(uint32_t*)(sm + PQ_WH + base)     = packhh(h0, h1);
        *(uint32_t*)(sm + PQ_WH + base + 4) = packhh(h2, h3);
        *(uint32_t*)(sm + PQ_WL + base)     = packh(v.x - __half2float(h0), v.y - __half2float(h1));
        *(uint32_t*)(sm + PQ_WL + base + 4) = packh(v.z - __half2float(h2), v.w - __half2float(h3));
    }

    float acc[8][4];
#pragma unroll
    for (int i = 0; i < 8; i++)
#pragma unroll
        for (int j = 0; j < 4; j++) acc[i][j] = 0.f;

    for (int kc = 0; kc < 4; kc++) {
        __syncthreads();
#pragma unroll
        for (int it = 0; it < 4; it++) {
            int idx = it * 256 + tid;
            int r = idx >> 3, j = idx & 7;
            size_t go = ((size_t)(b * NN + n0 + r)) * CC + kc * 64 + j * 8;
            cpa16(smem_u32(sm + PQ_XH + r * 144 + j * 16), xh + go);
            cpa16(smem_u32(sm + PQ_XL + r * 144 + j * 16), xl + go);
        }
        cp_commit();
        cp_wait<0>();
        __syncthreads();

        const int rowA = wid * 16 + g;
        uint32_t Ah[4][4], Al[4][4];
#pragma unroll
        for (int kf = 0; kf < 4; kf++) {
            int w0 = (kf * 8 + tg) * 4;
            const char* ph = sm + PQ_XH + rowA * 144 + w0;
            const char* pl = sm + PQ_XL + rowA * 144 + w0;
            Ah[kf][0] = *(const uint32_t*)ph;
            Ah[kf][1] = *(const uint32_t*)(ph + 8 * 144);
            Ah[kf][2] = *(const uint32_t*)(ph + 16);
            Ah[kf][3] = *(const uint32_t*)(ph + 8 * 144 + 16);
            Al[kf][0] = *(const uint32_t*)pl;
            Al[kf][1] = *(const uint32_t*)(pl + 8 * 144);
            Al[kf][2] = *(const uint32_t*)(pl + 16);
            Al[kf][3] = *(const uint32_t*)(pl + 8 * 144 + 16);
        }
#pragma unroll
        for (int nf = 0; nf < 8; nf++) {
#pragma unroll
            for (int kf = 0; kf < 4; kf++) {
                int w0 = kc * 128 + (kf * 8 + tg) * 4;
                const char* pb  = sm + PQ_WH + (nf * 8 + g) * 528 + w0;
                const char* pbl = sm + PQ_WL + (nf * 8 + g) * 528 + w0;
                uint32_t Bh[2] = {*(const uint32_t*)pb,  *(const uint32_t*)(pb + 16)};
                uint32_t Bl[2] = {*(const uint32_t*)pbl, *(const uint32_t*)(pbl + 16)};
                mma_f16(acc[nf], Ah[kf], Bh);
                mma_f16(acc[nf], Al[kf], Bh);
                mma_f16(acc[nf], Ah[kf], Bl);
            }
        }
    }

    const int nA = n0 + wid * 16 + g;
#pragma unroll
    for (int nf = 0; nf < 8; nf++) {
        bool isq = nf < 4;
        int d = (isq ? nf : nf - 4) * 8 + tg * 2;
        const float* bias = isq ? bq : bk;
        __half* oh = isq ? qh : kh;
        __half* ol = isq ? ql : kl;
        float sc = isq ? 1.44269504088896f : 1.0f;   // log2(e) folded into q
        float b0 = bias[d], b1 = bias[d + 1];
        float v0 = (acc[nf][0] + b0) * sc, v1 = (acc[nf][1] + b1) * sc;
        float v2 = (acc[nf][2] + b0) * sc, v3 = (acc[nf][3] + b1) * sc;
        __half h0 = __float2half_rn(v0), h1 = __float2half_rn(v1);
        __half h2 = __float2half_rn(v2), h3 = __float2half_rn(v3);
        size_t o0 = ((size_t)(b * NN + nA)) * DD + d;
        size_t o1 = ((size_t)(b * NN + nA + 8)) * DD + d;
        *(uint32_t*)(oh + o0) = packhh(h0, h1);
        *(uint32_t*)(ol + o0) = packh(v0 - __half2float(h0), v1 - __half2float(h1));
        *(uint32_t*)(oh + o1) = packhh(h2, h3);
        *(uint32_t*)(ol + o1) = packh(v2 - __half2float(h2), v3 - __half2float(h3));
    }
}

// ---------------------------------------------------------------------------
// proj_v_mma: v = W x + b via fp16 HMMA (3-term). Output fp16 [b][c][n].
// ---------------------------------------------------------------------------
__global__ void __launch_bounds__(256) proj_v_mma(
    const float* __restrict__ wv, const float* __restrict__ bv,
    const __half* __restrict__ xh, const __half* __restrict__ xl,
    __half* __restrict__ vh)
{
    extern __shared__ char sm[];
    const int tid = threadIdx.x, lane = tid & 31, wid = tid >> 5;
    const int g = lane >> 2, tg = lane & 3;
    const int b = blockIdx.z, c0 = blockIdx.y * 128, n0 = blockIdx.x * 128;
    const int wm = wid >> 1, wn = wid & 1;

    float acc[2][8][4];
#pragma unroll
    for (int m = 0; m < 2; m++)
#pragma unroll
        for (int i = 0; i < 8; i++)
#pragma unroll
            for (int j = 0; j < 4; j++) acc[m][i][j] = 0.f;

    for (int kc = 0; kc < 4; kc++) {
        __syncthreads();
#pragma unroll
        for (int it = 0; it < 8; it++) {
            int idx4 = it * 256 + tid;
            int row = idx4 >> 4, col4 = idx4 & 15;
            float4 v = *(const float4*)(wv + (size_t)(c0 + row) * CC + kc * 64 + col4 * 4);
            __half h0 = __float2half_rn(v.x), h1 = __float2half_rn(v.y);
            __half h2 = __float2half_rn(v.z), h3 = __float2half_rn(v.w);
            uint32_t base = row * 144 + col4 * 8;
            *(uint32_t*)(sm + PV_WH + base)     = packhh(h0, h1);
            *(uint32_t*)(sm + PV_WH + base + 4) = packhh(h2, h3);
            *(uint32_t*)(sm + PV_WL + base)     = packh(v.x - __half2float(h0), v.y - __half2float(h1));
            *(uint32_t*)(sm + PV_WL + base + 4) = packh(v.z - __half2float(h2), v.w - __half2float(h3));
        }
#pragma unroll
        for (int it = 0; it < 4; it++) {
            int idx = it * 256 + tid;
            int r = idx >> 3, j = idx & 7;
            size_t go = ((size_t)(b * NN + n0 + r)) * CC + kc * 64 + j * 8;
            cpa16(smem_u32(sm + PV_XH + r * 144 + j * 16), xh + go);
            cpa16(smem_u32(sm + PV_XL + r * 144 + j * 16), xl + go);
        }
        cp_commit();
        cp_wait<0>();
        __syncthreads();

#pragma unroll
        for (int kf = 0; kf < 4; kf++) {
            int w0 = (kf * 8 + tg) * 4;
            uint32_t Ah[2][4], Al[2][4];
#pragma unroll
            for (int mf = 0; mf < 2; mf++) {
                int rowA = wm * 32 + mf * 16 + g;
                const char* ph = sm + PV_WH + rowA * 144 + w0;
                const char* pl = sm + PV_WL + rowA * 144 + w0;
                Ah[mf][0] = *(const uint32_t*)ph;
                Ah[mf][1] = *(const uint32_t*)(ph + 8 * 144);
                Ah[mf][2] = *(const uint32_t*)(ph + 16);
                Ah[mf][3] = *(const uint32_t*)(ph + 8 * 144 + 16);
                Al[mf][0] = *(const uint32_t*)pl;
                Al[mf][1] = *(const uint32_t*)(pl + 8 * 144);
                Al[mf][2] = *(const uint32_t*)(pl + 16);
                Al[mf][3] = *(const uint32_t*)(pl + 8 * 144 + 16);
            }
#pragma unroll
            for (int nf = 0; nf < 8; nf++) {
                int rowB = wn * 64 + nf * 8 + g;
                const char* pb  = sm + PV_XH + rowB * 144 + w0;
                const char* pbl = sm + PV_XL + rowB * 144 + w0;
                uint32_t Bh[2] = {*(const uint32_t*)pb,  *(const uint32_t*)(pb + 16)};
                uint32_t Bl[2] = {*(const uint32_t*)pbl, *(const uint32_t*)(pbl + 16)};
#pragma unroll
                for (int mf = 0; mf < 2; mf++) {
                    mma_f16(acc[mf][nf], Ah[mf], Bh);
                    mma_f16(acc[mf][nf], Al[mf], Bh);
                    mma_f16(acc[mf][nf], Ah[mf], Bl);
                }
            }
        }
    }

#pragma unroll
    for (int mf = 0; mf < 2; mf++) {
        int c = c0 + wm * 32 + mf * 16 + g;
        float b0 = bv[c], b8 = bv[c + 8];
#pragma unroll
        for (int nf = 0; nf < 8; nf++) {
            int n = n0 + wn * 64 + nf * 8 + tg * 2;
            *(uint32_t*)(vh + ((size_t)(b * CC + c)) * NN + n) =
                packh(acc[mf][nf][0] + b0, acc[mf][nf][1] + b0);
            *(uint32_t*)(vh + ((size_t)(b * CC + c + 8)) * NN + n) =
                packh(acc[mf][nf][2] + b8, acc[mf][nf][3] + b8);
        }
    }
}

// per-thread share of one K/V tile load (10 cp.async of 16B)
__device__ __forceinline__ void load_kv(char* smp, int b, int m0, int buf, int tid) {
#pragma unroll
    for (int it = 0; it < 2; it++) {
        int idx = tid + it * 256;
        int mat = idx >> 8, r = (idx >> 2) & 63, j = idx & 3;
        const __half* src = (mat ? g_kl : g_kh) +
            ((size_t)(b * NN + m0 + r)) * DD + j * 8;
        cpa16(smem_u32(smp + K_OFF(buf, mat) + r * KSTR + j * 16), src);
    }
#pragma unroll
    for (int it = 0; it < 8; it++) {
        int idx = tid + it * 256;
        int r = idx >> 3, j = idx & 7;
        const __half* src = g_vh + ((size_t)(b * CC + r)) * NN + m0 + j * 8;
        cpa16(smem_u32(smp + V_OFF(buf) + r * VSTR + j * 16), src);
    }
}

// ---------------------------------------------------------------------------
// Flash attention: fp16 HMMA, exp2 online softmax; exp interleaved with PV
// by kf-slice; lazy rescale with shfl-free common-path check.
// ---------------------------------------------------------------------------
__global__ void __launch_bounds__(256, 1) flash_mma(
    const float* __restrict__ x, const float* __restrict__ gamma,
    float* __restrict__ out)
{
    extern __shared__ char smp[];
    const int tid  = threadIdx.x;
    const int lane = tid & 31;
    const int wid  = tid >> 5;
    const int wr   = wid >> 1;
    const int wc   = wid & 1;
    const int g    = lane >> 2;
    const int tg   = lane & 3;
    const int b  = blockIdx.y;
    const int q0 = blockIdx.x * BQ;

#pragma unroll
    for (int it = 0; it < 2; it++) {
        int idx = tid + it * 256;
        int mat = idx >> 8, r = (idx >> 2) & 63, j = idx & 3;
        const __half* src = (mat ? g_ql : g_qh) +
            ((size_t)(b * NN + q0 + r)) * DD + j * 8;
        cpa16(smem_u32(smp + (mat ? QL_OFF : QH_OFF) + r * QSTR + j * 16), src);
    }
    load_kv(smp, b, 0, 0, tid);
    cp_commit();
    cp_wait<0>();
    __syncthreads();

    uint32_t QhA[2][4], QlA[2][4];
    {
        int rowA = wr * 16 + g, rowB = rowA + 8;
#pragma unroll
        for (int kf = 0; kf < 2; kf++) {
            int w0 = (kf * 8 + tg) * 4;
            QhA[kf][0] = *(const uint32_t*)(smp + QH_OFF + rowA * QSTR + w0);
            QhA[kf][1] = *(const uint32_t*)(smp + QH_OFF + rowB * QSTR + w0);
            QhA[kf][2] = *(const uint32_t*)(smp + QH_OFF + rowA * QSTR + w0 + 16);
            QhA[kf][3] = *(const uint32_t*)(smp + QH_OFF + rowB * QSTR + w0 + 16);
            QlA[kf][0] = *(const uint32_t*)(smp + QL_OFF + rowA * QSTR + w0);
            QlA[kf][1] = *(const uint32_t*)(smp + QL_OFF + rowB * QSTR + w0);
            QlA[kf][2] = *(const uint32_t*)(smp + QL_OFF + rowA * QSTR + w0 + 16);
            QlA[kf][3] = *(const uint32_t*)(smp + QL_OFF + rowB * QSTR + w0 + 16);
        }
    }

    float O[16][4];
#pragma unroll
    for (int i = 0; i < 16; i++)
#pragma unroll
        for (int j = 0; j < 4; j++) O[i][j] = 0.f;
    float lsumA = 0.f, lsumB = 0.f;
    float mA = -1e30f, mB = -1e30f;
    float Sst[8][4];

    for (int t = 0; t < NT; t++) {
        const int buf = t & 1;
        if (t) cp_wait<0>();
        __syncthreads();
        if (t + 1 < NT) { load_kv(smp, b, (t + 1) * BK, buf ^ 1, tid); cp_commit(); }

        // ---- S (3 fp16 split terms, log2-scaled) + per-thread tile max ----
        const char* kh = smp + K_OFF(buf, 0);
        const char* kl = smp + K_OFF(buf, 1);
        float tmA = -1e30f, tmB = -1e30f;
#pragma unroll
        for (int nt = 0; nt < 8; nt++) {
            int krow = nt * 8 + g;
            uint32_t KhB[2][2], KlB[2][2];
#pragma unroll
            for (int kf = 0; kf < 2; kf++) {
                int w0 = (kf * 8 + tg) * 4;
                KhB[kf][0] = *(const uint32_t*)(kh + krow * KSTR + w0);
                KhB[kf][1] = *(const uint32_t*)(kh + krow * KSTR + w0 + 16);
                KlB[kf][0] = *(const uint32_t*)(kl + krow * KSTR + w0);
                KlB[kf][1] = *(const uint32_t*)(kl + krow * KSTR + w0 + 16);
            }
            float S[4] = {0.f, 0.f, 0.f, 0.f};
            mma_f16(S, QhA[0], KhB[0]); mma_f16(S, QhA[1], KhB[1]);
            mma_f16(S, QlA[0], KhB[0]); mma_f16(S, QlA[1], KhB[1]);
            mma_f16(S, QhA[0], KlB[0]); mma_f16(S, QhA[1], KlB[1]);
            Sst[nt][0] = S[0]; Sst[nt][1] = S[1];
            Sst[nt][2] = S[2]; Sst[nt][3] = S[3];
            tmA = fmaxf(tmA, fmaxf(S[0], S[1]));
            tmB = fmaxf(tmB, fmaxf(S[2], S[3]));
        }

        // ---- lazy rescale: per-thread check, shfls only in rare branch ----
        bool upd = (tmA > mA + 2.0f) || (tmB > mB + 2.0f);
        if (__ballot_sync(0xffffffffu, upd)) {
            tmA = fmaxf(tmA, __shfl_xor_sync(0xffffffffu, tmA, 1));
            tmA = fmaxf(tmA, __shfl_xor_sync(0xffffffffu, tmA, 2));
            tmB = fmaxf(tmB, __shfl_xor_sync(0xffffffffu, tmB, 1));
            tmB = fmaxf(tmB, __shfl_xor_sync(0xffffffffu, tmB, 2));
            float mAn = fmaxf(mA, tmA), mBn = fmaxf(mB, tmB);
            float cA = exp2f(mA - mAn), cB = exp2f(mB - mBn);
            mA = mAn; mB = mBn;
            lsumA *= cA; lsumB *= cB;
#pragma unroll
            for (int i = 0; i < 16; i++) {
                O[i][0] *= cA; O[i][1] *= cA;
                O[i][2] *= cB; O[i][3] *= cB;
            }
        }

        // ---- interleaved: exp2 (8 per slice) + PV slice kf=grp (16 MMAs) ----
        const char* vh = smp + V_OFF(buf);
#pragma unroll
        for (int grp = 0; grp < 4; grp++) {
            float p0 = exp2f(Sst[2*grp][0] - mA),   p1 = exp2f(Sst[2*grp][1] - mA);
            float p2 = exp2f(Sst[2*grp][2] - mB),   p3 = exp2f(Sst[2*grp][3] - mB);
            float p4 = exp2f(Sst[2*grp+1][0] - mA), p5 = exp2f(Sst[2*grp+1][1] - mA);
            float p6 = exp2f(Sst[2*grp+1][2] - mB), p7 = exp2f(Sst[2*grp+1][3] - mB);
            lsumA += (p0 + p1) + (p4 + p5);
            lsumB += (p2 + p3) + (p6 + p7);
            uint32_t Ah[4] = {packh(p0, p1), packh(p2, p3), packh(p4, p5), packh(p6, p7)};
            const int w0 = (grp * 8 + tg) * 4;
#pragma unroll
            for (int nt = 0; nt < 16; nt++) {
                int crow = wc * 128 + nt * 8 + g;
                uint32_t VhB[2];
                VhB[0] = *(const uint32_t*)(vh + crow * VSTR + w0);
                VhB[1] = *(const uint32_t*)(vh + crow * VSTR + w0 + 16);
                mma_f16(O[nt], Ah, VhB);
            }
        }
    }

    // ---- normalize + epilogue ----
    lsumA += __shfl_xor_sync(0xffffffffu, lsumA, 1);
    lsumA += __shfl_xor_sync(0xffffffffu, lsumA, 2);
    lsumB += __shfl_xor_sync(0xffffffffu, lsumB, 1);
    lsumB += __shfl_xor_sync(0xffffffffu, lsumB, 2);
    const float gm = gamma[0];
    const float scA = gm / lsumA;
    const float scB = gm / lsumB;

    __syncthreads();
    float* stage = (float*)(smp + STAGE_OFF);
    {
        int q = wr * 16 + g;
#pragma unroll
        for (int nt = 0; nt < 16; nt++) {
            int c = wc * 128 + nt * 8 + tg * 2;
            stage[q * OSTR + c]           = O[nt][0] * scA;
            stage[q * OSTR + c + 1]       = O[nt][1] * scA;
            stage[(q + 8) * OSTR + c]     = O[nt][2] * scB;
            stage[(q + 8) * OSTR + c + 1] = O[nt][3] * scB;
        }
    }
    __syncthreads();

    {
        int c = tid;
        const float* xr  = x   + ((size_t)(b * CC + c)) * NN + q0;
        float*       orw = out + ((size_t)(b * CC + c)) * NN + q0;
#pragma unroll 4
        for (int n4 = 0; n4 < 16; n4++) {
            float4 xv = *(const float4*)(xr + n4 * 4);
            float4 o;
            o.x = stage[(n4 * 4 + 0) * OSTR + c] + xv.x;
            o.y = stage[(n4 * 4 + 1) * OSTR + c] + xv.y;
            o.z = stage[(n4 * 4 + 2) * OSTR + c] + xv.z;
            o.w = stage[(n4 * 4 + 3) * OSTR + c] + xv.w;
            *(float4*)(orw + n4 * 4) = o;
        }
    }
}

// ---------------------------------------------------------------------------
extern "C" void kernel_launch(void* const* d_in, const int* in_sizes, int n_in,
                              void* d_out, int out_size)
{
    const float* x     = (const float*)d_in[0];
    const float* wq    = (const float*)d_in[1];
    const float* bq    = (const float*)d_in[2];
    const float* wk    = (const float*)d_in[3];
    const float* bk    = (const float*)d_in[4];
    const float* wv    = (const float*)d_in[5];
    const float* bv    = (const float*)d_in[6];
    const float* gamma = (const float*)d_in[7];
    float* out = (float*)d_out;

    __half *xhp, *xlp, *qh, *ql, *kh, *kl, *vh;
    cudaGetSymbolAddress((void**)&xhp, g_xh);
    cudaGetSymbolAddress((void**)&xlp, g_xl);
    cudaGetSymbolAddress((void**)&qh, g_qh);
    cudaGetSymbolAddress((void**)&ql, g_ql);
    cudaGetSymbolAddress((void**)&kh, g_kh);
    cudaGetSymbolAddress((void**)&kl, g_kl);
    cudaGetSymbolAddress((void**)&vh, g_vh);

    dim3 blk(256);
    split_x<<<dim3(NN / 64, CC / 64, NB), blk>>>(x, xhp, xlp);

    cudaFuncSetAttribute(proj_qk_mma, cudaFuncAttributeMaxDynamicSharedMemorySize, PQ_SMEM);
    proj_qk_mma<<<dim3(NN / 128, NB), blk, PQ_SMEM>>>(wq, bq, wk, bk, xhp, xlp, qh, ql, kh, kl);

    cudaFuncSetAttribute(proj_v_mma, cudaFuncAttributeMaxDynamicSharedMemorySize, PV_SMEM);
    proj_v_mma<<<dim3(NN / 128, CC / 128, NB), blk, PV_SMEM>>>(wv, bv, xhp, xlp, vh);

    cudaFuncSetAttribute(flash_mma, cudaFuncAttributeMaxDynamicSharedMemorySize, SMEM_BYTES);
    flash_mma<<<dim3(NN / BQ, NB), blk, SMEM_BYTES>>>(x, gamma, out);
}

// round 15
// speedup vs baseline: 2.0244x; 1.1592x over previous
#include <cuda_runtime.h>
#include <cuda_fp16.h>
#include <cstdint>

#define NB 8
#define CC 256
#define NN 4096
#define DD 32
#define BQ 64
#define BK 64
#define NT (NN / BK)

// fp16 operands (q pre-scaled by log2e; K single fp16 — 2-term S)
__device__ __align__(128) __half g_xh[(size_t)NB * NN * CC];  // xT [b][n][c]
__device__ __align__(128) __half g_xl[(size_t)NB * NN * CC];
__device__ __align__(128) __half g_qh[(size_t)NB * NN * DD];
__device__ __align__(128) __half g_ql[(size_t)NB * NN * DD];
__device__ __align__(128) __half g_kh[(size_t)NB * NN * DD];
__device__ __align__(128) __half g_vh[(size_t)NB * CC * NN];  // [b][c][n]

// ---- flash smem (triple-buffered K/V) ----
#define QSTR 80
#define KSTR 80
#define VSTR 144
#define OSTR 260
#define QH_OFF 0
#define QL_OFF 5120
#define K_OFF3(i) (10240 + (i) * 5120)    // 3 bufs, ends 25600
#define V_OFF3(i) (25600 + (i) * 36864)   // 3 bufs, ends 136192
#define STAGE_OFF 25600                   // reuses V region (66560 <= 110592)
#define SMEM_BYTES 136192
// ---- proj_qk_mma smem ----
#define PQ_WH 0
#define PQ_WL 33792
#define PQ_XH 67584
#define PQ_XL 86016
#define PQ_SMEM 104448
// ---- proj_v_mma smem ----
#define PV_WH 0
#define PV_WL 18432
#define PV_XH 36864
#define PV_XL 55296
#define PV_SMEM 73728

// ---- helpers ----
__device__ __forceinline__ uint32_t smem_u32(const void* p) {
    uint32_t a;
    asm("{ .reg .u64 t; cvta.to.shared.u64 t, %1; cvt.u32.u64 %0, t; }" : "=r"(a) : "l"(p));
    return a;
}
__device__ __forceinline__ void cpa16(uint32_t dst, const void* src) {
    asm volatile("cp.async.cg.shared.global [%0], [%1], 16;" :: "r"(dst), "l"(src) : "memory");
}
__device__ __forceinline__ void cp_commit() { asm volatile("cp.async.commit_group;" ::: "memory"); }
template <int N> __device__ __forceinline__ void cp_wait() {
    asm volatile("cp.async.wait_group %0;" :: "n"(N) : "memory");
}
__device__ __forceinline__ void mma_f16(float* d, const uint32_t* a, const uint32_t* b) {
    asm volatile(
        "mma.sync.aligned.m16n8k16.row.col.f32.f16.f16.f32 "
        "{%0,%1,%2,%3}, {%4,%5,%6,%7}, {%8,%9}, {%0,%1,%2,%3};"
        : "+f"(d[0]), "+f"(d[1]), "+f"(d[2]), "+f"(d[3])
        : "r"(a[0]), "r"(a[1]), "r"(a[2]), "r"(a[3]), "r"(b[0]), "r"(b[1]));
}
__device__ __forceinline__ uint32_t packh(float a, float b) {
    __half2 t; t.x = __float2half_rn(a); t.y = __float2half_rn(b);
    return *(uint32_t*)&t;
}
__device__ __forceinline__ uint32_t packhh(__half a, __half b) {
    __half2 t; t.x = a; t.y = b;
    return *(uint32_t*)&t;
}

// ---------------------------------------------------------------------------
// split_x: x fp32 [b][c][n] -> xh/xl fp16 transposed [b][n][c]
// ---------------------------------------------------------------------------
__global__ void __launch_bounds__(256) split_x(
    const float* __restrict__ x, __half* __restrict__ xh, __half* __restrict__ xl)
{
    __shared__ float tile[64][65];
    const int tid = threadIdx.x;
    const int n0 = blockIdx.x * 64, c0 = blockIdx.y * 64, b = blockIdx.z;
#pragma unroll
    for (int it = 0; it < 16; it++) {
        int r = it * 4 + (tid >> 6);
        int col = tid & 63;
        tile[r][col] = x[((size_t)(b * CC + c0 + r)) * NN + n0 + col];
    }
    __syncthreads();
#pragma unroll
    for (int it = 0; it < 8; it++) {
        int idx = it * 256 + tid;
        int nrow = idx >> 5;
        int cp = idx & 31;
        float a0 = tile[cp * 2][nrow];
        float a1 = tile[cp * 2 + 1][nrow];
        __half h0 = __float2half_rn(a0), h1 = __float2half_rn(a1);
        size_t o = ((size_t)(b * NN + n0 + nrow)) * CC + c0 + cp * 2;
        *(uint32_t*)(xh + o) = packhh(h0, h1);
        *(uint32_t*)(xl + o) = packh(a0 - __half2float(h0), a1 - __half2float(h1));
    }
}

// ---------------------------------------------------------------------------
// proj_qk_mma: q/k = W x + b via fp16 HMMA (3-term). q scaled by log2e.
// q stores hi+lo; k stores hi only (2-term S).
// ---------------------------------------------------------------------------
__global__ void __launch_bounds__(256) proj_qk_mma(
    const float* __restrict__ wq, const float* __restrict__ bq,
    const float* __restrict__ wk, const float* __restrict__ bk,
    const __half* __restrict__ xh, const __half* __restrict__ xl,
    __half* __restrict__ qh, __half* __restrict__ ql,
    __half* __restrict__ kh)
{
    extern __shared__ char sm[];
    const int tid = threadIdx.x, lane = tid & 31, wid = tid >> 5;
    const int g = lane >> 2, tg = lane & 3;
    const int b = blockIdx.y, n0 = blockIdx.x * 128;

#pragma unroll
    for (int it = 0; it < 16; it++) {
        int idx4 = it * 256 + tid;
        int row = idx4 >> 6, col4 = idx4 & 63;
        const float* src = (row < 32) ? (wq + (size_t)row * CC + col4 * 4)
                                      : (wk + (size_t)(row - 32) * CC + col4 * 4);
        float4 v = *(const float4*)src;
        __half h0 = __float2half_rn(v.x), h1 = __float2half_rn(v.y);
        __half h2 = __float2half_rn(v.z), h3 = __float2half_rn(v.w);
        uint32_t base = row * 528 + col4 * 8;
        *(uint32_t*)(sm + PQ_WH + base)     = packhh(h0, h1);
        *(uint32_t*)(sm + PQ_WH + base + 4) = packhh(h2, h3);
        *(uint32_t*)(sm + PQ_WL + base)     = packh(v.x - __half2float(h0), v.y - __half2float(h1));
        *(uint32_t*)(sm + PQ_WL + base + 4) = packh(v.z - __half2float(h2), v.w - __half2float(h3));
    }

    float acc[8][4];
#pragma unroll
    for (int i = 0; i < 8; i++)
#pragma unroll
        for (int j = 0; j < 4; j++) acc[i][j] = 0.f;

    for (int kc = 0; kc < 4; kc++) {
        __syncthreads();
#pragma unroll
        for (int it = 0; it < 4; it++) {
            int idx = it * 256 + tid;
            int r = idx >> 3, j = idx & 7;
            size_t go = ((size_t)(b * NN + n0 + r)) * CC + kc * 64 + j * 8;
            cpa16(smem_u32(sm + PQ_XH + r * 144 + j * 16), xh + go);
            cpa16(smem_u32(sm + PQ_XL + r * 144 + j * 16), xl + go);
        }
        cp_commit();
        cp_wait<0>();
        __syncthreads();

        const int rowA = wid * 16 + g;
        uint32_t Ah[4][4], Al[4][4];
#pragma unroll
        for (int kf = 0; kf < 4; kf++) {
            int w0 = (kf * 8 + tg) * 4;
            const char* ph = sm + PQ_XH + rowA * 144 + w0;
            const char* pl = sm + PQ_XL + rowA * 144 + w0;
            Ah[kf][0] = *(const uint32_t*)ph;
            Ah[kf][1] = *(const uint32_t*)(ph + 8 * 144);
            Ah[kf][2] = *(const uint32_t*)(ph + 16);
            Ah[kf][3] = *(const uint32_t*)(ph + 8 * 144 + 16);
            Al[kf][0] = *(const uint32_t*)pl;
            Al[kf][1] = *(const uint32_t*)(pl + 8 * 144);
            Al[kf][2] = *(const uint32_t*)(pl + 16);
            Al[kf][3] = *(const uint32_t*)(pl + 8 * 144 + 16);
        }
#pragma unroll
        for (int nf = 0; nf < 8; nf++) {
#pragma unroll
            for (int kf = 0; kf < 4; kf++) {
                int w0 = kc * 128 + (kf * 8 + tg) * 4;
                const char* pb  = sm + PQ_WH + (nf * 8 + g) * 528 + w0;
                const char* pbl = sm + PQ_WL + (nf * 8 + g) * 528 + w0;
                uint32_t Bh[2] = {*(const uint32_t*)pb,  *(const uint32_t*)(pb + 16)};
                uint32_t Bl[2] = {*(const uint32_t*)pbl, *(const uint32_t*)(pbl + 16)};
                mma_f16(acc[nf], Ah[kf], Bh);
                mma_f16(acc[nf], Al[kf], Bh);
                mma_f16(acc[nf], Ah[kf], Bl);
            }
        }
    }

    const int nA = n0 + wid * 16 + g;
#pragma unroll
    for (int nf = 0; nf < 8; nf++) {
        bool isq = nf < 4;
        int d = (isq ? nf : nf - 4) * 8 + tg * 2;
        const float* bias = isq ? bq : bk;
        __half* oh = isq ? qh : kh;
        float sc = isq ? 1.44269504088896f : 1.0f;   // log2(e) folded into q
        float b0 = bias[d], b1 = bias[d + 1];
        float v0 = (acc[nf][0] + b0) * sc, v1 = (acc[nf][1] + b1) * sc;
        float v2 = (acc[nf][2] + b0) * sc, v3 = (acc[nf][3] + b1) * sc;
        __half h0 = __float2half_rn(v0), h1 = __float2half_rn(v1);
        __half h2 = __float2half_rn(v2), h3 = __float2half_rn(v3);
        size_t o0 = ((size_t)(b * NN + nA)) * DD + d;
        size_t o1 = ((size_t)(b * NN + nA + 8)) * DD + d;
        *(uint32_t*)(oh + o0) = packhh(h0, h1);
        *(uint32_t*)(oh + o1) = packhh(h2, h3);
        if (isq) {   // lo residue needed for q only
            *(uint32_t*)(ql + o0) = packh(v0 - __half2float(h0), v1 - __half2float(h1));
            *(uint32_t*)(ql + o1) = packh(v2 - __half2float(h2), v3 - __half2float(h3));
        }
    }
}

// ---------------------------------------------------------------------------
// proj_v_mma: v = W x + b via fp16 HMMA (3-term). Output fp16 [b][c][n].
// ---------------------------------------------------------------------------
__global__ void __launch_bounds__(256) proj_v_mma(
    const float* __restrict__ wv, const float* __restrict__ bv,
    const __half* __restrict__ xh, const __half* __restrict__ xl,
    __half* __restrict__ vh)
{
    extern __shared__ char sm[];
    const int tid = threadIdx.x, lane = tid & 31, wid = tid >> 5;
    const int g = lane >> 2, tg = lane & 3;
    const int b = blockIdx.z, c0 = blockIdx.y * 128, n0 = blockIdx.x * 128;
    const int wm = wid >> 1, wn = wid & 1;

    float acc[2][8][4];
#pragma unroll
    for (int m = 0; m < 2; m++)
#pragma unroll
        for (int i = 0; i < 8; i++)
#pragma unroll
            for (int j = 0; j < 4; j++) acc[m][i][j] = 0.f;

    for (int kc = 0; kc < 4; kc++) {
        __syncthreads();
#pragma unroll
        for (int it = 0; it < 8; it++) {
            int idx4 = it * 256 + tid;
            int row = idx4 >> 4, col4 = idx4 & 15;
            float4 v = *(const float4*)(wv + (size_t)(c0 + row) * CC + kc * 64 + col4 * 4);
            __half h0 = __float2half_rn(v.x), h1 = __float2half_rn(v.y);
            __half h2 = __float2half_rn(v.z), h3 = __float2half_rn(v.w);
            uint32_t base = row * 144 + col4 * 8;
            *(uint32_t*)(sm + PV_WH + base)     = packhh(h0, h1);
            *(uint32_t*)(sm + PV_WH + base + 4) = packhh(h2, h3);
            *(uint32_t*)(sm + PV_WL + base)     = packh(v.x - __half2float(h0), v.y - __half2float(h1));
            *(uint32_t*)(sm + PV_WL + base + 4) = packh(v.z - __half2float(h2), v.w - __half2float(h3));
        }
#pragma unroll
        for (int it = 0; it < 4; it++) {
            int idx = it * 256 + tid;
            int r = idx >> 3, j = idx & 7;
            size_t go = ((size_t)(b * NN + n0 + r)) * CC + kc * 64 + j * 8;
            cpa16(smem_u32(sm + PV_XH + r * 144 + j * 16), xh + go);
            cpa16(smem_u32(sm + PV_XL + r * 144 + j * 16), xl + go);
        }
        cp_commit();
        cp_wait<0>();
        __syncthreads();

#pragma unroll
        for (int kf = 0; kf < 4; kf++) {
            int w0 = (kf * 8 + tg) * 4;
            uint32_t Ah[2][4], Al[2][4];
#pragma unroll
            for (int mf = 0; mf < 2; mf++) {
                int rowA = wm * 32 + mf * 16 + g;
                const char* ph = sm + PV_WH + rowA * 144 + w0;
                const char* pl = sm + PV_WL + rowA * 144 + w0;
                Ah[mf][0] = *(const uint32_t*)ph;
                Ah[mf][1] = *(const uint32_t*)(ph + 8 * 144);
                Ah[mf][2] = *(const uint32_t*)(ph + 16);
                Ah[mf][3] = *(const uint32_t*)(ph + 8 * 144 + 16);
                Al[mf][0] = *(const uint32_t*)pl;
                Al[mf][1] = *(const uint32_t*)(pl + 8 * 144);
                Al[mf][2] = *(const uint32_t*)(pl + 16);
                Al[mf][3] = *(const uint32_t*)(pl + 8 * 144 + 16);
            }
#pragma unroll
            for (int nf = 0; nf < 8; nf++) {
                int rowB = wn * 64 + nf * 8 + g;
                const char* pb  = sm + PV_XH + rowB * 144 + w0;
                const char* pbl = sm + PV_XL + rowB * 144 + w0;
                uint32_t Bh[2] = {*(const uint32_t*)pb,  *(const uint32_t*)(pb + 16)};
                uint32_t Bl[2] = {*(const uint32_t*)pbl, *(const uint32_t*)(pbl + 16)};
#pragma unroll
                for (int mf = 0; mf < 2; mf++) {
                    mma_f16(acc[mf][nf], Ah[mf], Bh);
                    mma_f16(acc[mf][nf], Al[mf], Bh);
                    mma_f16(acc[mf][nf], Ah[mf], Bl);
                }
            }
        }
    }

#pragma unroll
    for (int mf = 0; mf < 2; mf++) {
        int c = c0 + wm * 32 + mf * 16 + g;
        float b0 = bv[c], b8 = bv[c + 8];
#pragma unroll
        for (int nf = 0; nf < 8; nf++) {
            int n = n0 + wn * 64 + nf * 8 + tg * 2;
            *(uint32_t*)(vh + ((size_t)(b * CC + c)) * NN + n) =
                packh(acc[mf][nf][0] + b0, acc[mf][nf][1] + b0);
            *(uint32_t*)(vh + ((size_t)(b * CC + c + 8)) * NN + n) =
                packh(acc[mf][nf][2] + b8, acc[mf][nf][3] + b8);
        }
    }
}

// K tile (hi only): 64 rows x 4 chunks = 256 -> 1 cp.async/thread
__device__ __forceinline__ void load_k(char* smp, int b, int m0, int buf, int tid) {
    int r = tid >> 2, j = tid & 3;
    const __half* src = g_kh + ((size_t)(b * NN + m0 + r)) * DD + j * 8;
    cpa16(smem_u32(smp + K_OFF3(buf) + r * KSTR + j * 16), src);
}
// V tile: 256 rows x 8 chunks = 2048 -> 8 cp.async/thread
__device__ __forceinline__ void load_v(char* smp, int b, int m0, int buf, int tid) {
#pragma unroll
    for (int it = 0; it < 8; it++) {
        int idx = tid + it * 256;
        int r = idx >> 3, j = idx & 7;
        const __half* src = g_vh + ((size_t)(b * CC + r)) * NN + m0 + j * 8;
        cpa16(smem_u32(smp + V_OFF3(buf) + r * VSTR + j * 16), src);
    }
}

// ---------------------------------------------------------------------------
// Flash attention: fp16 HMMA, exp2 online softmax, 2-term S,
// S(t+1) pipelined into PV(t) (register-only), triple-buffered K/V.
// ---------------------------------------------------------------------------
__global__ void __launch_bounds__(256, 1) flash_mma(
    const float* __restrict__ x, const float* __restrict__ gamma,
    float* __restrict__ out)
{
    extern __shared__ char smp[];
    const int tid  = threadIdx.x;
    const int lane = tid & 31;
    const int wid  = tid >> 5;
    const int wr   = wid >> 1;
    const int wc   = wid & 1;
    const int g    = lane >> 2;
    const int tg   = lane & 3;
    const int b  = blockIdx.y;
    const int q0 = blockIdx.x * BQ;

    // prologue group A: Q + K(0)
#pragma unroll
    for (int it = 0; it < 2; it++) {
        int idx = tid + it * 256;
        int mat = idx >> 8, r = (idx >> 2) & 63, j = idx & 3;
        const __half* src = (mat ? g_ql : g_qh) +
            ((size_t)(b * NN + q0 + r)) * DD + j * 8;
        cpa16(smem_u32(smp + (mat ? QL_OFF : QH_OFF) + r * QSTR + j * 16), src);
    }
    load_k(smp, b, 0, 0, tid);
    cp_commit();
    // prologue group B: K(1) + V(0)
    load_k(smp, b, BK, 1, tid);
    load_v(smp, b, 0, 0, tid);
    cp_commit();
    cp_wait<1>();          // group A done
    __syncthreads();

    uint32_t QhA[2][4], QlA[2][4];
    {
        int rowA = wr * 16 + g, rowB = rowA + 8;
#pragma unroll
        for (int kf = 0; kf < 2; kf++) {
            int w0 = (kf * 8 + tg) * 4;
            QhA[kf][0] = *(const uint32_t*)(smp + QH_OFF + rowA * QSTR + w0);
            QhA[kf][1] = *(const uint32_t*)(smp + QH_OFF + rowB * QSTR + w0);
            QhA[kf][2] = *(const uint32_t*)(smp + QH_OFF + rowA * QSTR + w0 + 16);
            QhA[kf][3] = *(const uint32_t*)(smp + QH_OFF + rowB * QSTR + w0 + 16);
            QlA[kf][0] = *(const uint32_t*)(smp + QL_OFF + rowA * QSTR + w0);
            QlA[kf][1] = *(const uint32_t*)(smp + QL_OFF + rowB * QSTR + w0);
            QlA[kf][2] = *(const uint32_t*)(smp + QL_OFF + rowA * QSTR + w0 + 16);
            QlA[kf][3] = *(const uint32_t*)(smp + QL_OFF + rowB * QSTR + w0 + 16);
        }
    }

    float O[16][4];
#pragma unroll
    for (int i = 0; i < 16; i++)
#pragma unroll
        for (int j = 0; j < 4; j++) O[i][j] = 0.f;
    float lsumA = 0.f, lsumB = 0.f;
    float mA = -1e30f, mB = -1e30f;
    float Sst[2][8][4];

    // S(0) from K buffer 0 -> Sst[0]
    {
        const char* kh = smp + K_OFF3(0);
#pragma unroll
        for (int nt = 0; nt < 8; nt++) {
            int krow = nt * 8 + g;
            uint32_t KhB[2][2];
#pragma unroll
            for (int kf = 0; kf < 2; kf++) {
                int w0 = (kf * 8 + tg) * 4;
                KhB[kf][0] = *(const uint32_t*)(kh + krow * KSTR + w0);
                KhB[kf][1] = *(const uint32_t*)(kh + krow * KSTR + w0 + 16);
            }
            float S[4] = {0.f, 0.f, 0.f, 0.f};
            mma_f16(S, QhA[0], KhB[0]); mma_f16(S, QhA[1], KhB[1]);
            mma_f16(S, QlA[0], KhB[0]); mma_f16(S, QlA[1], KhB[1]);
            Sst[0][nt][0] = S[0]; Sst[0][nt][1] = S[1];
            Sst[0][nt][2] = S[2]; Sst[0][nt][3] = S[3];
        }
    }

#pragma unroll 2
    for (int t = 0; t < NT; t++) {
        const int cur = t & 1, nxt = cur ^ 1;
        if (t + 2 < NT) load_k(smp, b, (t + 2) * BK, (t + 2) % 3, tid);
        if (t + 1 < NT) load_v(smp, b, (t + 1) * BK, (t + 1) % 3, tid);
        cp_commit();
        cp_wait<1>();      // G(t-1) done: K(t+1), V(t) resident
        __syncthreads();

        // ---- max + lazy rescale on Sst[cur] ----
        float tmA = -1e30f, tmB = -1e30f;
#pragma unroll
        for (int nt = 0; nt < 8; nt++) {
            tmA = fmaxf(tmA, fmaxf(Sst[cur][nt][0], Sst[cur][nt][1]));
            tmB = fmaxf(tmB, fmaxf(Sst[cur][nt][2], Sst[cur][nt][3]));
        }
        bool upd = (tmA > mA + 2.0f) || (tmB > mB + 2.0f);
        if (__ballot_sync(0xffffffffu, upd)) {
            tmA = fmaxf(tmA, __shfl_xor_sync(0xffffffffu, tmA, 1));
            tmA = fmaxf(tmA, __shfl_xor_sync(0xffffffffu, tmA, 2));
            tmB = fmaxf(tmB, __shfl_xor_sync(0xffffffffu, tmB, 1));
            tmB = fmaxf(tmB, __shfl_xor_sync(0xffffffffu, tmB, 2));
            float mAn = fmaxf(mA, tmA), mBn = fmaxf(mB, tmB);
            float cA = exp2f(mA - mAn), cB = exp2f(mB - mBn);
            mA = mAn; mB = mBn;
            lsumA *= cA; lsumB *= cB;
#pragma unroll
            for (int i = 0; i < 16; i++) {
                O[i][0] *= cA; O[i][1] *= cA;
                O[i][2] *= cB; O[i][3] *= cB;
            }
        }

        // ---- per grp: exp2(8) + PV slice (16 MMA, V(t)) + S(t+1) 2 nt (8 MMA) ----
        const char* vh  = smp + V_OFF3(t % 3);
        const char* khn = smp + K_OFF3((t + 1) % 3);
        const bool do_s = (t + 1 < NT);
#pragma unroll
        for (int grp = 0; grp < 4; grp++) {
            float p0 = exp2f(Sst[cur][2*grp][0] - mA),   p1 = exp2f(Sst[cur][2*grp][1] - mA);
            float p2 = exp2f(Sst[cur][2*grp][2] - mB),   p3 = exp2f(Sst[cur][2*grp][3] - mB);
            float p4 = exp2f(Sst[cur][2*grp+1][0] - mA), p5 = exp2f(Sst[cur][2*grp+1][1] - mA);
            float p6 = exp2f(Sst[cur][2*grp+1][2] - mB), p7 = exp2f(Sst[cur][2*grp+1][3] - mB);
            lsumA += (p0 + p1) + (p4 + p5);
            lsumB += (p2 + p3) + (p6 + p7);
            uint32_t Ah[4] = {packh(p0, p1), packh(p2, p3), packh(p4, p5), packh(p6, p7)};
            const int w0 = (grp * 8 + tg) * 4;
#pragma unroll
            for (int nt = 0; nt < 16; nt++) {
                int crow = wc * 128 + nt * 8 + g;
                uint32_t VhB[2];
                VhB[0] = *(const uint32_t*)(vh + crow * VSTR + w0);
                VhB[1] = *(const uint32_t*)(vh + crow * VSTR + w0 + 16);
                mma_f16(O[nt], Ah, VhB);
            }
            if (do_s) {
#pragma unroll
                for (int i = 0; i < 2; i++) {
                    int snt = 2 * grp + i;
                    int krow = snt * 8 + g;
                    uint32_t KhB[2][2];
#pragma unroll
                    for (int kf = 0; kf < 2; kf++) {
                        int kw0 = (kf * 8 + tg) * 4;
                        KhB[kf][0] = *(const uint32_t*)(khn + krow * KSTR + kw0);
                        KhB[kf][1] = *(const uint32_t*)(khn + krow * KSTR + kw0 + 16);
                    }
                    float S[4] = {0.f, 0.f, 0.f, 0.f};
                    mma_f16(S, QhA[0], KhB[0]); mma_f16(S, QhA[1], KhB[1]);
                    mma_f16(S, QlA[0], KhB[0]); mma_f16(S, QlA[1], KhB[1]);
                    Sst[nxt][snt][0] = S[0]; Sst[nxt][snt][1] = S[1];
                    Sst[nxt][snt][2] = S[2]; Sst[nxt][snt][3] = S[3];
                }
            }
        }
    }

    // ---- normalize + epilogue ----
    lsumA += __shfl_xor_sync(0xffffffffu, lsumA, 1);
    lsumA += __shfl_xor_sync(0xffffffffu, lsumA, 2);
    lsumB += __shfl_xor_sync(0xffffffffu, lsumB, 1);
    lsumB += __shfl_xor_sync(0xffffffffu, lsumB, 2);
    const float gm = gamma[0];
    const float scA = gm / lsumA;
    const float scB = gm / lsumB;

    __syncthreads();
    float* stage = (float*)(smp + STAGE_OFF);
    {
        int q = wr * 16 + g;
#pragma unroll
        for (int nt = 0; nt < 16; nt++) {
            int c = wc * 128 + nt * 8 + tg * 2;
            stage[q * OSTR + c]           = O[nt][0] * scA;
            stage[q * OSTR + c + 1]       = O[nt][1] * scA;
            stage[(q + 8) * OSTR + c]     = O[nt][2] * scB;
            stage[(q + 8) * OSTR + c + 1] = O[nt][3] * scB;
        }
    }
    __syncthreads();

    {
        int c = tid;
        const float* xr  = x   + ((size_t)(b * CC + c)) * NN + q0;
        float*       orw = out + ((size_t)(b * CC + c)) * NN + q0;
#pragma unroll 4
        for (int n4 = 0; n4 < 16; n4++) {
            float4 xv = *(const float4*)(xr + n4 * 4);
            float4 o;
            o.x = stage[(n4 * 4 + 0) * OSTR + c] + xv.x;
            o.y = stage[(n4 * 4 + 1) * OSTR + c] + xv.y;
            o.z = stage[(n4 * 4 + 2) * OSTR + c] + xv.z;
            o.w = stage[(n4 * 4 + 3) * OSTR + c] + xv.w;
            *(float4*)(orw + n4 * 4) = o;
        }
    }
}

// ---------------------------------------------------------------------------
extern "C" void kernel_launch(void* const* d_in, const int* in_sizes, int n_in,
                              void* d_out, int out_size)
{
    const float* x     = (const float*)d_in[0];
    const float* wq    = (const float*)d_in[1];
    const float* bq    = (const float*)d_in[2];
    const float* wk    = (const float*)d_in[3];
    const float* bk    = (const float*)d_in[4];
    const float* wv    = (const float*)d_in[5];
    const float* bv    = (const float*)d_in[6];
    const float* gamma = (const float*)d_in[7];
    float* out = (float*)d_out;

    __half *xhp, *xlp, *qh, *ql, *kh, *vh;
    cudaGetSymbolAddress((void**)&xhp, g_xh);
    cudaGetSymbolAddress((void**)&xlp, g_xl);
    cudaGetSymbolAddress((void**)&qh, g_qh);
    cudaGetSymbolAddress((void**)&ql, g_ql);
    cudaGetSymbolAddress((void**)&kh, g_kh);
    cudaGetSymbolAddress((void**)&vh, g_vh);

    dim3 blk(256);
    split_x<<<dim3(NN / 64, CC / 64, NB), blk>>>(x, xhp, xlp);

    cudaFuncSetAttribute(proj_qk_mma, cudaFuncAttributeMaxDynamicSharedMemorySize, PQ_SMEM);
    proj_qk_mma<<<dim3(NN / 128, NB), blk, PQ_SMEM>>>(wq, bq, wk, bk, xhp, xlp, qh, ql, kh);

    cudaFuncSetAttribute(proj_v_mma, cudaFuncAttributeMaxDynamicSharedMemorySize, PV_SMEM);
    proj_v_mma<<<dim3(NN / 128, CC / 128, NB), blk, PV_SMEM>>>(wv, bv, xhp, xlp, vh);

    cudaFuncSetAttribute(flash_mma, cudaFuncAttributeMaxDynamicSharedMemorySize, SMEM_BYTES);
    flash_mma<<<dim3(NN / BQ, NB), blk, SMEM_BYTES>>>(x, gamma, out);
}

// round 16
// speedup vs baseline: 2.1635x; 1.0687x over previous
#include <cuda_runtime.h>
#include <cuda_fp16.h>
#include <cstdint>

#define NB 8
#define CC 256
#define NN 4096
#define DD 32
#define BQ 64
#define BK 64
#define NT (NN / BK)

// fp16 operands (q pre-scaled by log2e; q/k single fp16 — 1-term S)
__device__ __align__(128) __half g_xh[(size_t)NB * NN * CC];  // xT [b][n][c]
__device__ __align__(128) __half g_xl[(size_t)NB * NN * CC];
__device__ __align__(128) __half g_qh[(size_t)NB * NN * DD];
__device__ __align__(128) __half g_kh[(size_t)NB * NN * DD];
__device__ __align__(128) __half g_vh[(size_t)NB * CC * NN];  // [b][c][n]

// ---- flash smem (triple-buffered K/V) ----
#define QSTR 80
#define KSTR 80
#define VSTR 144
#define OSTR 260
#define QH_OFF 0
#define K_OFF3(i) (5120 + (i) * 5120)     // 3 bufs, ends 20480
#define V_OFF3(i) (20480 + (i) * 36864)   // 3 bufs, ends 131072
#define STAGE_OFF 20480                   // reuses V region (66560 <= 110592)
#define SMEM_BYTES 131072
// ---- proj_qk_mma smem ----
#define PQ_WH 0
#define PQ_WL 33792
#define PQ_XH 67584
#define PQ_XL 86016
#define PQ_SMEM 104448
// ---- proj_v_mma smem ----
#define PV_WH 0
#define PV_WL 18432
#define PV_XH 36864
#define PV_XL 55296
#define PV_SMEM 73728

// ---- helpers ----
__device__ __forceinline__ uint32_t smem_u32(const void* p) {
    uint32_t a;
    asm("{ .reg .u64 t; cvta.to.shared.u64 t, %1; cvt.u32.u64 %0, t; }" : "=r"(a) : "l"(p));
    return a;
}
__device__ __forceinline__ void cpa16(uint32_t dst, const void* src) {
    asm volatile("cp.async.cg.shared.global [%0], [%1], 16;" :: "r"(dst), "l"(src) : "memory");
}
__device__ __forceinline__ void cp_commit() { asm volatile("cp.async.commit_group;" ::: "memory"); }
template <int N> __device__ __forceinline__ void cp_wait() {
    asm volatile("cp.async.wait_group %0;" :: "n"(N) : "memory");
}
__device__ __forceinline__ void mma_f16(float* d, const uint32_t* a, const uint32_t* b) {
    asm volatile(
        "mma.sync.aligned.m16n8k16.row.col.f32.f16.f16.f32 "
        "{%0,%1,%2,%3}, {%4,%5,%6,%7}, {%8,%9}, {%0,%1,%2,%3};"
        : "+f"(d[0]), "+f"(d[1]), "+f"(d[2]), "+f"(d[3])
        : "r"(a[0]), "r"(a[1]), "r"(a[2]), "r"(a[3]), "r"(b[0]), "r"(b[1]));
}
__device__ __forceinline__ uint32_t packh(float a, float b) {
    __half2 t; t.x = __float2half_rn(a); t.y = __float2half_rn(b);
    return *(uint32_t*)&t;
}
__device__ __forceinline__ uint32_t packhh(__half a, __half b) {
    __half2 t; t.x = a; t.y = b;
    return *(uint32_t*)&t;
}

// ---------------------------------------------------------------------------
// split_x: x fp32 [b][c][n] -> xh/xl fp16 transposed [b][n][c]
// ---------------------------------------------------------------------------
__global__ void __launch_bounds__(256) split_x(
    const float* __restrict__ x, __half* __restrict__ xh, __half* __restrict__ xl)
{
    __shared__ float tile[64][65];
    const int tid = threadIdx.x;
    const int n0 = blockIdx.x * 64, c0 = blockIdx.y * 64, b = blockIdx.z;
#pragma unroll
    for (int it = 0; it < 16; it++) {
        int r = it * 4 + (tid >> 6);
        int col = tid & 63;
        tile[r][col] = x[((size_t)(b * CC + c0 + r)) * NN + n0 + col];
    }
    __syncthreads();
#pragma unroll
    for (int it = 0; it < 8; it++) {
        int idx = it * 256 + tid;
        int nrow = idx >> 5;
        int cp = idx & 31;
        float a0 = tile[cp * 2][nrow];
        float a1 = tile[cp * 2 + 1][nrow];
        __half h0 = __float2half_rn(a0), h1 = __float2half_rn(a1);
        size_t o = ((size_t)(b * NN + n0 + nrow)) * CC + c0 + cp * 2;
        *(uint32_t*)(xh + o) = packhh(h0, h1);
        *(uint32_t*)(xl + o) = packh(a0 - __half2float(h0), a1 - __half2float(h1));
    }
}

// ---------------------------------------------------------------------------
// proj_qk_mma: q/k = W x + b via fp16 HMMA (3-term). q scaled by log2e.
// Both q and k store single fp16 (1-term S).
// ---------------------------------------------------------------------------
__global__ void __launch_bounds__(256) proj_qk_mma(
    const float* __restrict__ wq, const float* __restrict__ bq,
    const float* __restrict__ wk, const float* __restrict__ bk,
    const __half* __restrict__ xh, const __half* __restrict__ xl,
    __half* __restrict__ qh, __half* __restrict__ kh)
{
    extern __shared__ char sm[];
    const int tid = threadIdx.x, lane = tid & 31, wid = tid >> 5;
    const int g = lane >> 2, tg = lane & 3;
    const int b = blockIdx.y, n0 = blockIdx.x * 128;

#pragma unroll
    for (int it = 0; it < 16; it++) {
        int idx4 = it * 256 + tid;
        int row = idx4 >> 6, col4 = idx4 & 63;
        const float* src = (row < 32) ? (wq + (size_t)row * CC + col4 * 4)
                                      : (wk + (size_t)(row - 32) * CC + col4 * 4);
        float4 v = *(const float4*)src;
        __half h0 = __float2half_rn(v.x), h1 = __float2half_rn(v.y);
        __half h2 = __float2half_rn(v.z), h3 = __float2half_rn(v.w);
        uint32_t base = row * 528 + col4 * 8;
        *(uint32_t*)(sm + PQ_WH + base)     = packhh(h0, h1);
        *(uint32_t*)(sm + PQ_WH + base + 4) = packhh(h2, h3);
        *(uint32_t*)(sm + PQ_WL + base)     = packh(v.x - __half2float(h0), v.y - __half2float(h1));
        *(uint32_t*)(sm + PQ_WL + base + 4) = packh(v.z - __half2float(h2), v.w - __half2float(h3));
    }

    float acc[8][4];
#pragma unroll
    for (int i = 0; i < 8; i++)
#pragma unroll
        for (int j = 0; j < 4; j++) acc[i][j] = 0.f;

    for (int kc = 0; kc < 4; kc++) {
        __syncthreads();
#pragma unroll
        for (int it = 0; it < 4; it++) {
            int idx = it * 256 + tid;
            int r = idx >> 3, j = idx & 7;
            size_t go = ((size_t)(b * NN + n0 + r)) * CC + kc * 64 + j * 8;
            cpa16(smem_u32(sm + PQ_XH + r * 144 + j * 16), xh + go);
            cpa16(smem_u32(sm + PQ_XL + r * 144 + j * 16), xl + go);
        }
        cp_commit();
        cp_wait<0>();
        __syncthreads();

        const int rowA = wid * 16 + g;
        uint32_t Ah[4][4], Al[4][4];
#pragma unroll
        for (int kf = 0; kf < 4; kf++) {
            int w0 = (kf * 8 + tg) * 4;
            const char* ph = sm + PQ_XH + rowA * 144 + w0;
            const char* pl = sm + PQ_XL + rowA * 144 + w0;
            Ah[kf][0] = *(const uint32_t*)ph;
            Ah[kf][1] = *(const uint32_t*)(ph + 8 * 144);
            Ah[kf][2] = *(const uint32_t*)(ph + 16);
            Ah[kf][3] = *(const uint32_t*)(ph + 8 * 144 + 16);
            Al[kf][0] = *(const uint32_t*)pl;
            Al[kf][1] = *(const uint32_t*)(pl + 8 * 144);
            Al[kf][2] = *(const uint32_t*)(pl + 16);
            Al[kf][3] = *(const uint32_t*)(pl + 8 * 144 + 16);
        }
#pragma unroll
        for (int nf = 0; nf < 8; nf++) {
#pragma unroll
            for (int kf = 0; kf < 4; kf++) {
                int w0 = kc * 128 + (kf * 8 + tg) * 4;
                const char* pb  = sm + PQ_WH + (nf * 8 + g) * 528 + w0;
                const char* pbl = sm + PQ_WL + (nf * 8 + g) * 528 + w0;
                uint32_t Bh[2] = {*(const uint32_t*)pb,  *(const uint32_t*)(pb + 16)};
                uint32_t Bl[2] = {*(const uint32_t*)pbl, *(const uint32_t*)(pbl + 16)};
                mma_f16(acc[nf], Ah[kf], Bh);
                mma_f16(acc[nf], Al[kf], Bh);
                mma_f16(acc[nf], Ah[kf], Bl);
            }
        }
    }

    const int nA = n0 + wid * 16 + g;
#pragma unroll
    for (int nf = 0; nf < 8; nf++) {
        bool isq = nf < 4;
        int d = (isq ? nf : nf - 4) * 8 + tg * 2;
        const float* bias = isq ? bq : bk;
        __half* oh = isq ? qh : kh;
        float sc = isq ? 1.44269504088896f : 1.0f;   // log2(e) folded into q
        float b0 = bias[d], b1 = bias[d + 1];
        float v0 = (acc[nf][0] + b0) * sc, v1 = (acc[nf][1] + b1) * sc;
        float v2 = (acc[nf][2] + b0) * sc, v3 = (acc[nf][3] + b1) * sc;
        size_t o0 = ((size_t)(b * NN + nA)) * DD + d;
        size_t o1 = ((size_t)(b * NN + nA + 8)) * DD + d;
        *(uint32_t*)(oh + o0) = packh(v0, v1);
        *(uint32_t*)(oh + o1) = packh(v2, v3);
    }
}

// ---------------------------------------------------------------------------
// proj_v_mma: v = W x + b via fp16 HMMA (3-term). Output fp16 [b][c][n].
// ---------------------------------------------------------------------------
__global__ void __launch_bounds__(256) proj_v_mma(
    const float* __restrict__ wv, const float* __restrict__ bv,
    const __half* __restrict__ xh, const __half* __restrict__ xl,
    __half* __restrict__ vh)
{
    extern __shared__ char sm[];
    const int tid = threadIdx.x, lane = tid & 31, wid = tid >> 5;
    const int g = lane >> 2, tg = lane & 3;
    const int b = blockIdx.z, c0 = blockIdx.y * 128, n0 = blockIdx.x * 128;
    const int wm = wid >> 1, wn = wid & 1;

    float acc[2][8][4];
#pragma unroll
    for (int m = 0; m < 2; m++)
#pragma unroll
        for (int i = 0; i < 8; i++)
#pragma unroll
            for (int j = 0; j < 4; j++) acc[m][i][j] = 0.f;

    for (int kc = 0; kc < 4; kc++) {
        __syncthreads();
#pragma unroll
        for (int it = 0; it < 8; it++) {
            int idx4 = it * 256 + tid;
            int row = idx4 >> 4, col4 = idx4 & 15;
            float4 v = *(const float4*)(wv + (size_t)(c0 + row) * CC + kc * 64 + col4 * 4);
            __half h0 = __float2half_rn(v.x), h1 = __float2half_rn(v.y);
            __half h2 = __float2half_rn(v.z), h3 = __float2half_rn(v.w);
            uint32_t base = row * 144 + col4 * 8;
            *(uint32_t*)(sm + PV_WH + base)     = packhh(h0, h1);
            *(uint32_t*)(sm + PV_WH + base + 4) = packhh(h2, h3);
            *(uint32_t*)(sm + PV_WL + base)     = packh(v.x - __half2float(h0), v.y - __half2float(h1));
            *(uint32_t*)(sm + PV_WL + base + 4) = packh(v.z - __half2float(h2), v.w - __half2float(h3));
        }
#pragma unroll
        for (int it = 0; it < 4; it++) {
            int idx = it * 256 + tid;
            int r = idx >> 3, j = idx & 7;
            size_t go = ((size_t)(b * NN + n0 + r)) * CC + kc * 64 + j * 8;
            cpa16(smem_u32(sm + PV_XH + r * 144 + j * 16), xh + go);
            cpa16(smem_u32(sm + PV_XL + r * 144 + j * 16), xl + go);
        }
        cp_commit();
        cp_wait<0>();
        __syncthreads();

#pragma unroll
        for (int kf = 0; kf < 4; kf++) {
            int w0 = (kf * 8 + tg) * 4;
            uint32_t Ah[2][4], Al[2][4];
#pragma unroll
            for (int mf = 0; mf < 2; mf++) {
                int rowA = wm * 32 + mf * 16 + g;
                const char* ph = sm + PV_WH + rowA * 144 + w0;
                const char* pl = sm + PV_WL + rowA * 144 + w0;
                Ah[mf][0] = *(const uint32_t*)ph;
                Ah[mf][1] = *(const uint32_t*)(ph + 8 * 144);
                Ah[mf][2] = *(const uint32_t*)(ph + 16);
                Ah[mf][3] = *(const uint32_t*)(ph + 8 * 144 + 16);
                Al[mf][0] = *(const uint32_t*)pl;
                Al[mf][1] = *(const uint32_t*)(pl + 8 * 144);
                Al[mf][2] = *(const uint32_t*)(pl + 16);
                Al[mf][3] = *(const uint32_t*)(pl + 8 * 144 + 16);
            }
#pragma unroll
            for (int nf = 0; nf < 8; nf++) {
                int rowB = wn * 64 + nf * 8 + g;
                const char* pb  = sm + PV_XH + rowB * 144 + w0;
                const char* pbl = sm + PV_XL + rowB * 144 + w0;
                uint32_t Bh[2] = {*(const uint32_t*)pb,  *(const uint32_t*)(pb + 16)};
                uint32_t Bl[2] = {*(const uint32_t*)pbl, *(const uint32_t*)(pbl + 16)};
#pragma unroll
                for (int mf = 0; mf < 2; mf++) {
                    mma_f16(acc[mf][nf], Ah[mf], Bh);
                    mma_f16(acc[mf][nf], Al[mf], Bh);
                    mma_f16(acc[mf][nf], Ah[mf], Bl);
                }
            }
        }
    }

#pragma unroll
    for (int mf = 0; mf < 2; mf++) {
        int c = c0 + wm * 32 + mf * 16 + g;
        float b0 = bv[c], b8 = bv[c + 8];
#pragma unroll
        for (int nf = 0; nf < 8; nf++) {
            int n = n0 + wn * 64 + nf * 8 + tg * 2;
            *(uint32_t*)(vh + ((size_t)(b * CC + c)) * NN + n) =
                packh(acc[mf][nf][0] + b0, acc[mf][nf][1] + b0);
            *(uint32_t*)(vh + ((size_t)(b * CC + c + 8)) * NN + n) =
                packh(acc[mf][nf][2] + b8, acc[mf][nf][3] + b8);
        }
    }
}

// K tile: 64 rows x 4 chunks = 256 -> 1 cp.async/thread
__device__ __forceinline__ void load_k(char* smp, int b, int m0, int buf, int tid) {
    int r = tid >> 2, j = tid & 3;
    const __half* src = g_kh + ((size_t)(b * NN + m0 + r)) * DD + j * 8;
    cpa16(smem_u32(smp + K_OFF3(buf) + r * KSTR + j * 16), src);
}
// V tile: 256 rows x 8 chunks = 2048 -> 8 cp.async/thread
__device__ __forceinline__ void load_v(char* smp, int b, int m0, int buf, int tid) {
#pragma unroll
    for (int it = 0; it < 8; it++) {
        int idx = tid + it * 256;
        int r = idx >> 3, j = idx & 7;
        const __half* src = g_vh + ((size_t)(b * CC + r)) * NN + m0 + j * 8;
        cpa16(smem_u32(smp + V_OFF3(buf) + r * VSTR + j * 16), src);
    }
}

// ---------------------------------------------------------------------------
// Flash attention: fp16 HMMA, exp2 online softmax, 1-term S (80 HMMA/tile),
// S(t+1) register-pipelined into PV(t), triple-buffered K/V.
// ---------------------------------------------------------------------------
__global__ void __launch_bounds__(256, 1) flash_mma(
    const float* __restrict__ x, const float* __restrict__ gamma,
    float* __restrict__ out)
{
    extern __shared__ char smp[];
    const int tid  = threadIdx.x;
    const int lane = tid & 31;
    const int wid  = tid >> 5;
    const int wr   = wid >> 1;
    const int wc   = wid & 1;
    const int g    = lane >> 2;
    const int tg   = lane & 3;
    const int b  = blockIdx.y;
    const int q0 = blockIdx.x * BQ;

    // prologue group A: Q + K(0)
    {
        int r = (tid >> 2) & 63, j = tid & 3;
        const __half* src = g_qh + ((size_t)(b * NN + q0 + r)) * DD + j * 8;
        cpa16(smem_u32(smp + QH_OFF + r * QSTR + j * 16), src);
    }
    load_k(smp, b, 0, 0, tid);
    cp_commit();
    // prologue group B: K(1) + V(0)
    load_k(smp, b, BK, 1, tid);
    load_v(smp, b, 0, 0, tid);
    cp_commit();
    cp_wait<1>();          // group A done
    __syncthreads();

    uint32_t QhA[2][4];
    {
        int rowA = wr * 16 + g, rowB = rowA + 8;
#pragma unroll
        for (int kf = 0; kf < 2; kf++) {
            int w0 = (kf * 8 + tg) * 4;
            QhA[kf][0] = *(const uint32_t*)(smp + QH_OFF + rowA * QSTR + w0);
            QhA[kf][1] = *(const uint32_t*)(smp + QH_OFF + rowB * QSTR + w0);
            QhA[kf][2] = *(const uint32_t*)(smp + QH_OFF + rowA * QSTR + w0 + 16);
            QhA[kf][3] = *(const uint32_t*)(smp + QH_OFF + rowB * QSTR + w0 + 16);
        }
    }

    float O[16][4];
#pragma unroll
    for (int i = 0; i < 16; i++)
#pragma unroll
        for (int j = 0; j < 4; j++) O[i][j] = 0.f;
    float lsumA = 0.f, lsumB = 0.f;
    float mA = -1e30f, mB = -1e30f;
    float Sst[2][8][4];

    // S(0) from K buffer 0 -> Sst[0]
    {
        const char* kh = smp + K_OFF3(0);
#pragma unroll
        for (int nt = 0; nt < 8; nt++) {
            int krow = nt * 8 + g;
            uint32_t KhB[2][2];
#pragma unroll
            for (int kf = 0; kf < 2; kf++) {
                int w0 = (kf * 8 + tg) * 4;
                KhB[kf][0] = *(const uint32_t*)(kh + krow * KSTR + w0);
                KhB[kf][1] = *(const uint32_t*)(kh + krow * KSTR + w0 + 16);
            }
            float S[4] = {0.f, 0.f, 0.f, 0.f};
            mma_f16(S, QhA[0], KhB[0]); mma_f16(S, QhA[1], KhB[1]);
            Sst[0][nt][0] = S[0]; Sst[0][nt][1] = S[1];
            Sst[0][nt][2] = S[2]; Sst[0][nt][3] = S[3];
        }
    }

#pragma unroll 2
    for (int t = 0; t < NT; t++) {
        const int cur = t & 1, nxt = cur ^ 1;
        if (t + 2 < NT) load_k(smp, b, (t + 2) * BK, (t + 2) % 3, tid);
        if (t + 1 < NT) load_v(smp, b, (t + 1) * BK, (t + 1) % 3, tid);
        cp_commit();
        cp_wait<1>();      // G(t-1) done: K(t+1), V(t) resident
        __syncthreads();

        // ---- max + lazy rescale on Sst[cur] ----
        float tmA = -1e30f, tmB = -1e30f;
#pragma unroll
        for (int nt = 0; nt < 8; nt++) {
            tmA = fmaxf(tmA, fmaxf(Sst[cur][nt][0], Sst[cur][nt][1]));
            tmB = fmaxf(tmB, fmaxf(Sst[cur][nt][2], Sst[cur][nt][3]));
        }
        bool upd = (tmA > mA + 2.0f) || (tmB > mB + 2.0f);
        if (__ballot_sync(0xffffffffu, upd)) {
            tmA = fmaxf(tmA, __shfl_xor_sync(0xffffffffu, tmA, 1));
            tmA = fmaxf(tmA, __shfl_xor_sync(0xffffffffu, tmA, 2));
            tmB = fmaxf(tmB, __shfl_xor_sync(0xffffffffu, tmB, 1));
            tmB = fmaxf(tmB, __shfl_xor_sync(0xffffffffu, tmB, 2));
            float mAn = fmaxf(mA, tmA), mBn = fmaxf(mB, tmB);
            float cA = exp2f(mA - mAn), cB = exp2f(mB - mBn);
            mA = mAn; mB = mBn;
            lsumA *= cA; lsumB *= cB;
#pragma unroll
            for (int i = 0; i < 16; i++) {
                O[i][0] *= cA; O[i][1] *= cA;
                O[i][2] *= cB; O[i][3] *= cB;
            }
        }

        // ---- per grp: exp2(8) + PV slice (16 MMA, V(t)) + S(t+1) 2 nt (4 MMA) ----
        const char* vh  = smp + V_OFF3(t % 3);
        const char* khn = smp + K_OFF3((t + 1) % 3);
        const bool do_s = (t + 1 < NT);
#pragma unroll
        for (int grp = 0; grp < 4; grp++) {
            float p0 = exp2f(Sst[cur][2*grp][0] - mA),   p1 = exp2f(Sst[cur][2*grp][1] - mA);
            float p2 = exp2f(Sst[cur][2*grp][2] - mB),   p3 = exp2f(Sst[cur][2*grp][3] - mB);
            float p4 = exp2f(Sst[cur][2*grp+1][0] - mA), p5 = exp2f(Sst[cur][2*grp+1][1] - mA);
            float p6 = exp2f(Sst[cur][2*grp+1][2] - mB), p7 = exp2f(Sst[cur][2*grp+1][3] - mB);
            lsumA += (p0 + p1) + (p4 + p5);
            lsumB += (p2 + p3) + (p6 + p7);
            uint32_t Ah[4] = {packh(p0, p1), packh(p2, p3), packh(p4, p5), packh(p6, p7)};
            const int w0 = (grp * 8 + tg) * 4;
#pragma unroll
            for (int nt = 0; nt < 16; nt++) {
                int crow = wc * 128 + nt * 8 + g;
                uint32_t VhB[2];
                VhB[0] = *(const uint32_t*)(vh + crow * VSTR + w0);
                VhB[1] = *(const uint32_t*)(vh + crow * VSTR + w0 + 16);
                mma_f16(O[nt], Ah, VhB);
            }
            if (do_s) {
#pragma unroll
                for (int i = 0; i < 2; i++) {
                    int snt = 2 * grp + i;
                    int krow = snt * 8 + g;
                    uint32_t KhB[2][2];
#pragma unroll
                    for (int kf = 0; kf < 2; kf++) {
                        int kw0 = (kf * 8 + tg) * 4;
                        KhB[kf][0] = *(const uint32_t*)(khn + krow * KSTR + kw0);
                        KhB[kf][1] = *(const uint32_t*)(khn + krow * KSTR + kw0 + 16);
                    }
                    float S[4] = {0.f, 0.f, 0.f, 0.f};
                    mma_f16(S, QhA[0], KhB[0]); mma_f16(S, QhA[1], KhB[1]);
                    Sst[nxt][snt][0] = S[0]; Sst[nxt][snt][1] = S[1];
                    Sst[nxt][snt][2] = S[2]; Sst[nxt][snt][3] = S[3];
                }
            }
        }
    }

    // ---- normalize + epilogue ----
    lsumA += __shfl_xor_sync(0xffffffffu, lsumA, 1);
    lsumA += __shfl_xor_sync(0xffffffffu, lsumA, 2);
    lsumB += __shfl_xor_sync(0xffffffffu, lsumB, 1);
    lsumB += __shfl_xor_sync(0xffffffffu, lsumB, 2);
    const float gm = gamma[0];
    const float scA = gm / lsumA;
    const float scB = gm / lsumB;

    __syncthreads();
    float* stage = (float*)(smp + STAGE_OFF);
    {
        int q = wr * 16 + g;
#pragma unroll
        for (int nt = 0; nt < 16; nt++) {
            int c = wc * 128 + nt * 8 + tg * 2;
            stage[q * OSTR + c]           = O[nt][0] * scA;
            stage[q * OSTR + c + 1]       = O[nt][1] * scA;
            stage[(q + 8) * OSTR + c]     = O[nt][2] * scB;
            stage[(q + 8) * OSTR + c + 1] = O[nt][3] * scB;
        }
    }
    __syncthreads();

    {
        int c = tid;
        const float* xr  = x   + ((size_t)(b * CC + c)) * NN + q0;
        float*       orw = out + ((size_t)(b * CC + c)) * NN + q0;
#pragma unroll 4
        for (int n4 = 0; n4 < 16; n4++) {
            float4 xv = *(const float4*)(xr + n4 * 4);
            float4 o;
            o.x = stage[(n4 * 4 + 0) * OSTR + c] + xv.x;
            o.y = stage[(n4 * 4 + 1) * OSTR + c] + xv.y;
            o.z = stage[(n4 * 4 + 2) * OSTR + c] + xv.z;
            o.w = stage[(n4 * 4 + 3) * OSTR + c] + xv.w;
            *(float4*)(orw + n4 * 4) = o;
        }
    }
}

// ---------------------------------------------------------------------------
extern "C" void kernel_launch(void* const* d_in, const int* in_sizes, int n_in,
                              void* d_out, int out_size)
{
    const float* x     = (const float*)d_in[0];
    const float* wq    = (const float*)d_in[1];
    const float* bq    = (const float*)d_in[2];
    const float* wk    = (const float*)d_in[3];
    const float* bk    = (const float*)d_in[4];
    const float* wv    = (const float*)d_in[5];
    const float* bv    = (const float*)d_in[6];
    const float* gamma = (const float*)d_in[7];
    float* out = (float*)d_out;

    __half *xhp, *xlp, *qh, *kh, *vh;
    cudaGetSymbolAddress((void**)&xhp, g_xh);
    cudaGetSymbolAddress((void**)&xlp, g_xl);
    cudaGetSymbolAddress((void**)&qh, g_qh);
    cudaGetSymbolAddress((void**)&kh, g_kh);
    cudaGetSymbolAddress((void**)&vh, g_vh);

    dim3 blk(256);
    split_x<<<dim3(NN / 64, CC / 64, NB), blk>>>(x, xhp, xlp);

    cudaFuncSetAttribute(proj_qk_mma, cudaFuncAttributeMaxDynamicSharedMemorySize, PQ_SMEM);
    proj_qk_mma<<<dim3(NN / 128, NB), blk, PQ_SMEM>>>(wq, bq, wk, bk, xhp, xlp, qh, kh);

    cudaFuncSetAttribute(proj_v_mma, cudaFuncAttributeMaxDynamicSharedMemorySize, PV_SMEM);
    proj_v_mma<<<dim3(NN / 128, CC / 128, NB), blk, PV_SMEM>>>(wv, bv, xhp, xlp, vh);

    cudaFuncSetAttribute(flash_mma, cudaFuncAttributeMaxDynamicSharedMemorySize, SMEM_BYTES);
    flash_mma<<<dim3(NN / BQ, NB), blk, SMEM_BYTES>>>(x, gamma, out);
}